// round 11
// baseline (speedup 1.0000x reference)
#include <cuda_runtime.h>
#include <cuda_fp16.h>
#include <math.h>
#include <stdint.h>

// Problem constants
#define BB   8
#define TT   1024
#define DIN  256
#define CH   1024   // D_H1
#define OO   1024   // D_H2
#define KW   9

// Packed-panel format for GEMM operands (fp16, 2 bytes):
//   operand [R][K] (K-major) -> tiles of 128 rows x 32 k,
//   byte offset = ((r>>7)*nks + (k>>5))*SEGB + (r&127)*PROWB + (k&31)*2
#define PROWB 80
#define SEGB  10240                     // 128 * 80
#define PB_X   (8 * 8 * SEGB)           // per-batch packed x   [1024][256]
#define PB_1K  (8 * 32 * SEGB)          // per-batch packed [1024][1024]
#define PB_W2  (2 * 32 * SEGB)          // packed w2 [256][1024]

__device__ __forceinline__ size_t pk_off(int r, int k, int nks) {
    return (size_t)((r >> 7) * nks + (k >> 5)) * SEGB +
           (size_t)(r & 127) * PROWB + (size_t)(k & 31) * 2;
}

// Scratch (device globals — no allocation allowed)
__device__ __half g_h [BB * CH * TT];    // mish(w1(x)), [b][c][t], fp16
__device__ float g_pwn[BB * OO];
__device__ float g_dwn[BB * KW];
__device__ __align__(128) char g_xph [BB * PB_X];    // B of GEMM1
__device__ __align__(128) char g_w1ph[8 * 8 * SEGB]; // A of GEMM1
__device__ __align__(128) char g_w2ph[PB_W2];        // B of GEMM3
__device__ __align__(128) char g_pTph[BB * PB_1K];   // B of GEMM2
__device__ __align__(128) char g_yTph[BB * PB_1K];   // A of GEMM2
__device__ __align__(128) char g_y2ph[BB * PB_1K];   // A of GEMM3

__device__ __forceinline__ float mishf(float v) {
    float sp = (v > 20.f) ? v : log1pf(__expf(v));
    return v * tanhf(sp);
}

// ---------------------------------------------------------------------------
// Fused preprocessing: one launch, grid-partitioned.
// ---------------------------------------------------------------------------
#define NB_DWN 72
#define NB_PWN 256
#define NB_SX  2048
#define NB_SW1 256
#define NB_SW2 256
#define NB_TC  8192
#define NB_TOT (NB_DWN + NB_PWN + NB_SX + NB_SW1 + NB_SW2 + NB_TC)

__global__ void __launch_bounds__(256)
prep_kernel(const float* __restrict__ x,
            const float* __restrict__ d_w,
            const float* __restrict__ p_w,
            const float* __restrict__ w1_w,
            const float* __restrict__ w2_w,
            char* __restrict__ xph, char* __restrict__ w1ph,
            char* __restrict__ w2ph, char* __restrict__ pTph) {
    __shared__ float tile[32][33];
    const int blk = blockIdx.x, tid = threadIdx.x;

    if (blk < NB_DWN) {
        int b = blk / KW, k = blk % KW;
        float* red = &tile[0][0];
        float s = 0.f;
        for (int c = tid; c < CH; c += 256) {
            float v = d_w[((long)b * CH + c) * KW + k];
            s += v * v;
        }
        red[tid] = s;
        __syncthreads();
        for (int off = 128; off > 0; off >>= 1) {
            if (tid < off) red[tid] += red[tid + off];
            __syncthreads();
        }
        if (tid == 0)
            g_dwn[b * KW + k] = 1.f / fmaxf(sqrtf(red[0]), 1e-12f);
        return;
    }
    if (blk < NB_DWN + NB_PWN) {
        int idx = blk - NB_DWN;
        int b  = idx / (OO / 32);
        int o0 = (idx % (OO / 32)) * 32;
        int oi = tid & 31, cg = tid >> 5;
        int o = o0 + oi;
        float s = 0.f;
        for (int c = cg; c < CH; c += 8) {
            float v = p_w[((long)b * CH + c) * OO + o];
            s += v * v;
        }
        tile[cg][oi] = s;
        __syncthreads();
        if (cg == 0) {
            float t = 0.f;
            #pragma unroll
            for (int j = 0; j < 8; j++) t += tile[j][oi];
            g_pwn[b * OO + o] = 1.f / fmaxf(sqrtf(t), 1e-12f);
        }
        return;
    }
    if (blk < NB_DWN + NB_PWN + NB_SX + NB_SW1 + NB_SW2) {
        const float* src;
        char* dst;
        int K, R;
        long pb;
        int i;
        if (blk < NB_DWN + NB_PWN + NB_SX) {
            i = (blk - NB_DWN - NB_PWN) * 256 + tid;
            src = x; dst = xph; K = DIN; R = TT; pb = PB_X;
        } else if (blk < NB_DWN + NB_PWN + NB_SX + NB_SW1) {
            i = (blk - NB_DWN - NB_PWN - NB_SX) * 256 + tid;
            src = w1_w; dst = w1ph; K = DIN; R = CH; pb = 0;
        } else {
            i = (blk - NB_DWN - NB_PWN - NB_SX - NB_SW1) * 256 + tid;
            src = w2_w; dst = w2ph; K = OO; R = DIN; pb = 0;
        }
        long e = (long)i * 4;
        long perb = (long)R * K;
        int bb = (int)(e / perb);
        long rem = e - (long)bb * perb;
        int r = (int)(rem / K), k = (int)(rem % K);
        float4 v = ((const float4*)src)[i];
        __half2 hA, hB;
        hA.x = __float2half(v.x); hA.y = __float2half(v.y);
        hB.x = __float2half(v.z); hB.y = __float2half(v.w);
        size_t off = (size_t)bb * pb + pk_off(r, k, K >> 5);
        uint2 hw;
        hw.x = *(uint32_t*)&hA; hw.y = *(uint32_t*)&hB;
        *(uint2*)(dst + off) = hw;
        return;
    }
    {
        int idx = blk - (NB_DWN + NB_PWN + NB_SX + NB_SW1 + NB_SW2);
        int b   = idx >> 10;
        int rem = idx & 1023;
        int c0  = (rem & 31) * 32;
        int r0  = (rem >> 5) * 32;
        int tx = tid & 31, ty = tid >> 5;
        const float* s = p_w + ((size_t)b * 1024 + r0) * 1024 + c0;
        #pragma unroll
        for (int i = 0; i < 32; i += 8)
            tile[ty + i][tx] = s[(size_t)(ty + i) * 1024 + tx];
        __syncthreads();
        #pragma unroll
        for (int i = 0; i < 32; i += 8) {
            float v = tile[tx][ty + i];
            size_t off = (size_t)b * PB_1K + pk_off(c0 + ty + i, r0 + tx, 32);
            *(__half*)(pTph + off) = __float2half(v);
        }
    }
}

// ---------------------------------------------------------------------------
// Fused: depthwise conv (fp16 input) + transpose + fp16 quantize, packed out
// ---------------------------------------------------------------------------
__global__ void __launch_bounds__(256)
convT_kernel(const float* __restrict__ d_w, const float* __restrict__ d_g,
             const float* __restrict__ d_b, const float* __restrict__ p_g,
             char* __restrict__ hi) {
    __shared__ float tile[32][41];
    int b = blockIdx.z, c0 = blockIdx.y * 32, t0 = blockIdx.x * 32;
    int tid = threadIdx.y * 32 + threadIdx.x;

    const __half* hbase = g_h + ((size_t)b * CH + c0) * TT;
    #pragma unroll
    for (int i = tid; i < 32 * 40; i += 256) {
        int c = i / 40, j = i % 40;
        int t = t0 - 4 + j;
        tile[c][j] = (t >= 0 && t < TT)
                     ? __half2float(hbase[(size_t)c * TT + t]) : 0.f;
    }
    __syncthreads();

    int tx = threadIdx.x;
    int c  = c0 + tx;
    float gg   = d_g[b * CH + c];
    float pg   = p_g[b * CH + c];
    float bias = d_b[b * CH + c];
    float w[KW];
    #pragma unroll
    for (int k = 0; k < KW; k++)
        w[k] = d_w[((size_t)b * CH + c) * KW + k] * g_dwn[b * KW + k] * gg;

    #pragma unroll
    for (int i = 0; i < 4; i++) {
        int tl = threadIdx.y + i * 8;
        float acc = bias;
        #pragma unroll
        for (int k = 0; k < KW; k++) acc = fmaf(tile[tx][tl + k], w[k], acc);
        float v = acc * pg;
        size_t off = (size_t)b * PB_1K + pk_off(t0 + tl, c, 32);
        *(__half*)(hi + off) = __float2half(v);
    }
}

// ---------------------------------------------------------------------------
// PTX helpers
// ---------------------------------------------------------------------------
__device__ __forceinline__ uint32_t smem_u32(const void* p) {
    uint32_t a;
    asm("{ .reg .u64 t; cvta.to.shared.u64 t, %1; cvt.u32.u64 %0, t; }"
        : "=r"(a) : "l"(p));
    return a;
}

__device__ __forceinline__ void mbar_init(uint32_t m, uint32_t cnt) {
    asm volatile("mbarrier.init.shared.b64 [%0], %1;" :: "r"(m), "r"(cnt)
                 : "memory");
}

__device__ __forceinline__ void mbar_expect(uint32_t m, uint32_t tx) {
    asm volatile("mbarrier.arrive.expect_tx.shared.b64 _, [%0], %1;"
                 :: "r"(m), "r"(tx) : "memory");
}

__device__ __forceinline__ void mbar_arrive(uint32_t m) {
    asm volatile("mbarrier.arrive.shared.b64 _, [%0];" :: "r"(m) : "memory");
}

__device__ __forceinline__ void bulk_g2s(uint32_t dst, const void* src,
                                         uint32_t bytes, uint32_t mbar) {
    asm volatile(
        "cp.async.bulk.shared::cluster.global.mbarrier::complete_tx::bytes "
        "[%0], [%1], %2, [%3];"
        :: "r"(dst), "l"(src), "r"(bytes), "r"(mbar) : "memory");
}

__device__ __forceinline__ void mbar_wait(uint32_t m, uint32_t parity) {
    uint32_t done = 0;
    while (!done)
        asm volatile(
            "{ .reg .pred P; mbarrier.try_wait.parity.shared.b64 P, [%1], %2; "
            "selp.b32 %0,1,0,P; }"
            : "=r"(done) : "r"(m), "r"(parity) : "memory");
}

__device__ __forceinline__ void ldsm4(uint32_t* r, uint32_t a) {
    asm volatile("ldmatrix.sync.aligned.m8n8.x4.shared.b16 {%0,%1,%2,%3}, [%4];"
                 : "=r"(r[0]), "=r"(r[1]), "=r"(r[2]), "=r"(r[3]) : "r"(a));
}

__device__ __forceinline__ void mma16816(float* d, const uint32_t* a,
                                         const uint32_t* b) {
    asm volatile(
        "mma.sync.aligned.m16n8k16.row.col.f32.f16.f16.f32 "
        "{%0,%1,%2,%3}, {%4,%5,%6,%7}, {%8,%9}, {%0,%1,%2,%3};"
        : "+f"(d[0]), "+f"(d[1]), "+f"(d[2]), "+f"(d[3])
        : "r"(a[0]), "r"(a[1]), "r"(a[2]), "r"(a[3]), "r"(b[0]), "r"(b[1]));
}

// ---------------------------------------------------------------------------
// Single-pass fp16 GEMM, producer-consumer pipeline.
// Template NJ = j-tiles per warp (each 8 wide): CTA tile = 128 x (32*NJ).
//   NJ=4 -> 128x128 (GEMM1/2), NJ=2 -> 128x64 (GEMM3, 2x CTAs for wave fill).
// B fragments loaded 2 j's at a time via ldsm4 (fewer LDSM issues).
// EPI 1: fp16 C = mish(v + e1[m])
// EPI 2: packed fp16 C = v*e1[b*OO+n] + e2[b*OO+n]
// EPI 3: fp32 C = v + e1[n] + e2[b][m][n]
// ---------------------------------------------------------------------------
#define ASEG  SEGB                       // A: 128 rows
#define NSTG  4

template<int EPI, int NJ>
__global__ void __launch_bounds__(256, 2)
mma_gemm(const char* __restrict__ Ah, long sA,
         const char* __restrict__ Bh, long sB,
         void* __restrict__ C0, long sC,
         int M, int N, int K,
         const float* __restrict__ e1, const float* __restrict__ e2)
{
    constexpr int BN   = 32 * NJ;        // CTA n-tile
    constexpr int BSEG = BN * PROWB;     // B stage bytes
    constexpr int STG  = ASEG + BSEG;

    extern __shared__ __align__(128) char sm[];
    const uint32_t smb = smem_u32(sm);
    const uint32_t mbF = smb + NSTG * STG;
    const uint32_t mbE = mbF + NSTG * 8;
    const int tid = threadIdx.x, lane = tid & 31, wid = tid >> 5;
    const int b = blockIdx.z;
    const int m0 = blockIdx.y * 128, n0 = blockIdx.x * BN;
    const int wm = wid >> 2, wn = wid & 3;
    const int nk = K >> 5;

    const char* pAh = Ah + (size_t)b * sA + (size_t)(m0 >> 7) * nk * SEGB;
    const char* pBh = Bh + (size_t)b * sB + (size_t)(n0 >> 7) * nk * SEGB
                         + (size_t)(n0 & 127) * PROWB;

    if (tid < NSTG) {
        mbar_init(mbF + tid * 8, 1);
        mbar_init(mbE + tid * 8, 8);
    }
    __syncthreads();

    float acc[4][NJ][4];
    #pragma unroll
    for (int i = 0; i < 4; i++)
        #pragma unroll
        for (int j = 0; j < NJ; j++)
            #pragma unroll
            for (int r = 0; r < 4; r++) acc[i][j][r] = 0.f;

    auto issue = [&](int kc) {
        int s = kc & (NSTG - 1);
        uint32_t mb = mbF + s * 8;
        uint32_t sb = smb + s * STG;
        size_t go = (size_t)kc * SEGB;
        mbar_expect(mb, STG);
        bulk_g2s(sb,        pAh + go, ASEG, mb);
        bulk_g2s(sb + ASEG, pBh + go, BSEG, mb);
    };

    auto compute = [&](int s) {
        const uint32_t sb = smb + s * STG;
        #pragma unroll
        for (int ks = 0; ks < 2; ks++) {
            uint32_t ah[4][4], bh[NJ][2];
            #pragma unroll
            for (int i = 0; i < 4; i++) {
                uint32_t ad = sb +
                    (uint32_t)((wm * 64 + i * 16 + (lane & 15)) * PROWB) +
                    ks * 32 + (lane >> 4) * 16;
                ldsm4(ah[i], ad);
            }
            #pragma unroll
            for (int jj = 0; jj < NJ / 2; jj++) {
                uint32_t r[4];
                uint32_t bd = sb + ASEG +
                    (uint32_t)((wn * BN / 4 + jj * 16 + (lane & 15)) * PROWB) +
                    ks * 32 + (lane >> 4) * 16;
                ldsm4(r, bd);
                bh[jj * 2 + 0][0] = r[0]; bh[jj * 2 + 0][1] = r[2];
                bh[jj * 2 + 1][0] = r[1]; bh[jj * 2 + 1][1] = r[3];
            }
            #pragma unroll
            for (int i = 0; i < 4; i++)
                #pragma unroll
                for (int j = 0; j < NJ; j++)
                    mma16816(acc[i][j], ah[i], bh[j]);
        }
    };

    if (tid == 0) {
        #pragma unroll
        for (int p = 0; p < NSTG - 1; p++)
            if (p < nk) issue(p);
    }
    for (int kc = 0; kc < nk; kc++) {
        int s = kc & (NSTG - 1);
        mbar_wait(mbF + s * 8, (kc >> 2) & 1);
        compute(s);
        if (lane == 0) mbar_arrive(mbE + s * 8);
        int kn = kc + NSTG - 1;
        if (kn < nk && tid == 0) {
            int sn = kn & (NSTG - 1);
            if (kn >= NSTG)
                mbar_wait(mbE + sn * 8, ((kn - NSTG) >> 2) & 1);
            issue(kn);
        }
    }

    // --- epilogue ---
    const float* E1 = e1;
    const float* E2 = e2;
    if (EPI == 2) { E1 = e1 + b * OO; E2 = e2 + b * OO; }
    if (EPI == 3) { E2 = e2 + (size_t)b * M * N; }

    char* C0b = (char*)C0 + (size_t)b * sC;

    const int mrow0 = m0 + wm * 64;
    const int ncol0 = n0 + wn * (BN / 4);
    #pragma unroll
    for (int i = 0; i < 4; i++) {
        #pragma unroll
        for (int r = 0; r < 2; r++) {
            int m = mrow0 + i * 16 + (lane >> 2) + r * 8;
            #pragma unroll
            for (int j = 0; j < NJ; j++) {
                int n = ncol0 + j * 8 + (lane & 3) * 2;
                float v0 = acc[i][j][r * 2 + 0];
                float v1 = acc[i][j][r * 2 + 1];
                size_t off = (size_t)m * N + n;
                if (EPI == 1) {
                    float bb = E1[m];
                    __half2 hv;
                    hv.x = __float2half(mishf(v0 + bb));
                    hv.y = __float2half(mishf(v1 + bb));
                    *(__half2*)((__half*)C0b + off) = hv;
                } else if (EPI == 2) {
                    v0 = v0 * E1[n] + E2[n];
                    v1 = v1 * E1[n + 1] + E2[n + 1];
                    __half2 hv;
                    hv.x = __float2half(v0);
                    hv.y = __float2half(v1);
                    size_t po = pk_off(m, n, N >> 5);
                    *(uint32_t*)(C0b + po) = *(uint32_t*)&hv;
                } else {
                    float2 o;
                    o.x = v0 + E1[n]     + E2[off];
                    o.y = v1 + E1[n + 1] + E2[off + 1];
                    *(float2*)((float*)C0b + off) = o;
                }
            }
        }
    }
}

#define SMEM_OF(NJ_) (NSTG * (ASEG + 32 * (NJ_) * PROWB) + 2 * NSTG * 8)

// ---------------------------------------------------------------------------
extern "C" void kernel_launch(void* const* d_in, const int* in_sizes, int n_in,
                              void* d_out, int out_size) {
    const float* x    = (const float*)d_in[0];
    const float* d_w  = (const float*)d_in[1];
    const float* d_g  = (const float*)d_in[2];
    const float* d_b  = (const float*)d_in[3];
    const float* p_w  = (const float*)d_in[4];
    const float* p_g  = (const float*)d_in[5];
    const float* p_b  = (const float*)d_in[6];
    const float* w1_w = (const float*)d_in[7];
    const float* w1_b = (const float*)d_in[8];
    const float* w2_w = (const float*)d_in[9];
    const float* w2_b = (const float*)d_in[10];
    float* out = (float*)d_out;

    void *p_gh, *p_gpwn;
    void *p_xh, *p_w1h, *p_w2h, *p_pth, *p_yth, *p_y2h;
    cudaGetSymbolAddress(&p_gh,   g_h);
    cudaGetSymbolAddress(&p_gpwn, g_pwn);
    cudaGetSymbolAddress(&p_xh,   g_xph);
    cudaGetSymbolAddress(&p_w1h,  g_w1ph);
    cudaGetSymbolAddress(&p_w2h,  g_w2ph);
    cudaGetSymbolAddress(&p_pth,  g_pTph);
    cudaGetSymbolAddress(&p_yth,  g_yTph);
    cudaGetSymbolAddress(&p_y2h,  g_y2ph);
    float* gpwn = (float*)p_gpwn;

    cudaFuncSetAttribute((const void*)mma_gemm<1, 4>,
                         cudaFuncAttributeMaxDynamicSharedMemorySize,
                         SMEM_OF(4));
    cudaFuncSetAttribute((const void*)mma_gemm<2, 4>,
                         cudaFuncAttributeMaxDynamicSharedMemorySize,
                         SMEM_OF(4));
    cudaFuncSetAttribute((const void*)mma_gemm<3, 2>,
                         cudaFuncAttributeMaxDynamicSharedMemorySize,
                         SMEM_OF(2));

    // 1) fused preprocessing (norms + all input conversions), one launch
    prep_kernel<<<NB_TOT, 256>>>(x, d_w, p_w, w1_w, w2_w,
                                 (char*)p_xh, (char*)p_w1h,
                                 (char*)p_w2h, (char*)p_pth);

    // 2) GEMM1: h = mish(w1 . x + w1_b)   M=CH, N=TT, K=DIN  (fp16 out)
    {
        dim3 grid(TT / 128, CH / 128, BB);
        mma_gemm<1, 4><<<grid, 256, SMEM_OF(4)>>>(
            (char*)p_w1h, 0L,
            (char*)p_xh, (long)PB_X,
            p_gh, (long)CH * TT * 2,
            CH, TT, DIN, w1_b, nullptr);
    }

    // 3) fused conv + transpose + fp16 quantize -> yT packed
    {
        dim3 grid(TT / 32, CH / 32, BB);
        convT_kernel<<<grid, dim3(32, 8)>>>(d_w, d_g, d_b, p_g, (char*)p_yth);
    }

    // 4) GEMM2: y2 = (yT . pT)*pwn + p_b   M=TT, N=OO, K=CH  (packed fp16 out)
    {
        dim3 grid(OO / 128, TT / 128, BB);
        mma_gemm<2, 4><<<grid, 256, SMEM_OF(4)>>>(
            (char*)p_yth, (long)PB_1K,
            (char*)p_pth, (long)PB_1K,
            p_y2h, (long)PB_1K,
            TT, OO, CH, gpwn, p_b);
    }

    // 5) GEMM3: out = y2 . w2^T + w2_b + x   M=TT, N=DIN, K=OO
    //    128x64 CTA tiles -> 256 CTAs (fills the 296 co-residency slots)
    {
        dim3 grid(DIN / 64, TT / 128, BB);
        mma_gemm<3, 2><<<grid, 256, SMEM_OF(2)>>>(
            (char*)p_y2h, (long)PB_1K,
            (char*)p_w2h, 0L,
            out, (long)TT * DIN * 4,
            TT, DIN, OO, w2_b, x);
    }
}

// round 12
// speedup vs baseline: 1.0773x; 1.0773x over previous
#include <cuda_runtime.h>
#include <cuda_fp16.h>
#include <math.h>
#include <stdint.h>

// Problem constants
#define BB   8
#define TT   1024
#define DIN  256
#define CH   1024   // D_H1
#define OO   1024   // D_H2
#define KW   9

// Packed-panel format for GEMM operands (fp16, 2 bytes):
//   operand [R][K] (K-major) -> tiles of 128 rows x 32 k,
//   byte offset = ((r>>7)*nks + (k>>5))*SEGB + (r&127)*PROWB + (k&31)*2
#define PROWB 80
#define SEGB  10240                     // 128 * 80
#define PB_X   (8 * 8 * SEGB)           // per-batch packed x   [1024][256]
#define PB_1K  (8 * 32 * SEGB)          // per-batch packed [1024][1024]
#define PB_W2  (2 * 32 * SEGB)          // packed w2 [256][1024]

__device__ __forceinline__ size_t pk_off(int r, int k, int nks) {
    return (size_t)((r >> 7) * nks + (k >> 5)) * SEGB +
           (size_t)(r & 127) * PROWB + (size_t)(k & 31) * 2;
}

// Scratch (device globals — no allocation allowed)
__device__ __half g_h [BB * CH * TT];    // mish(w1(x)), [b][c][t], fp16
__device__ float g_pwn[BB * OO];
__device__ float g_dwn[BB * KW];
__device__ __align__(128) char g_xph [BB * PB_X];    // B of GEMM1
__device__ __align__(128) char g_w1ph[8 * 8 * SEGB]; // A of GEMM1
__device__ __align__(128) char g_w2ph[PB_W2];        // B of GEMM3
__device__ __align__(128) char g_pTph[BB * PB_1K];   // B of GEMM2
__device__ __align__(128) char g_yTph[BB * PB_1K];   // A of GEMM2
__device__ __align__(128) char g_y2ph[BB * PB_1K];   // A of GEMM3

__device__ __forceinline__ float mishf(float v) {
    float sp = (v > 20.f) ? v : log1pf(__expf(v));
    return v * tanhf(sp);
}

// ---------------------------------------------------------------------------
// Fused preprocessing: one launch, grid-partitioned.
// ---------------------------------------------------------------------------
#define NB_DWN 72
#define NB_PWN 256
#define NB_SX  2048
#define NB_SW1 256
#define NB_SW2 256
#define NB_TC  8192
#define NB_TOT (NB_DWN + NB_PWN + NB_SX + NB_SW1 + NB_SW2 + NB_TC)

__global__ void __launch_bounds__(256)
prep_kernel(const float* __restrict__ x,
            const float* __restrict__ d_w,
            const float* __restrict__ p_w,
            const float* __restrict__ w1_w,
            const float* __restrict__ w2_w,
            char* __restrict__ xph, char* __restrict__ w1ph,
            char* __restrict__ w2ph, char* __restrict__ pTph) {
    __shared__ float tile[32][33];
    const int blk = blockIdx.x, tid = threadIdx.x;

    if (blk < NB_DWN) {
        int b = blk / KW, k = blk % KW;
        float* red = &tile[0][0];
        float s = 0.f;
        for (int c = tid; c < CH; c += 256) {
            float v = d_w[((long)b * CH + c) * KW + k];
            s += v * v;
        }
        red[tid] = s;
        __syncthreads();
        for (int off = 128; off > 0; off >>= 1) {
            if (tid < off) red[tid] += red[tid + off];
            __syncthreads();
        }
        if (tid == 0)
            g_dwn[b * KW + k] = 1.f / fmaxf(sqrtf(red[0]), 1e-12f);
        return;
    }
    if (blk < NB_DWN + NB_PWN) {
        int idx = blk - NB_DWN;
        int b  = idx / (OO / 32);
        int o0 = (idx % (OO / 32)) * 32;
        int oi = tid & 31, cg = tid >> 5;
        int o = o0 + oi;
        float s = 0.f;
        for (int c = cg; c < CH; c += 8) {
            float v = p_w[((long)b * CH + c) * OO + o];
            s += v * v;
        }
        tile[cg][oi] = s;
        __syncthreads();
        if (cg == 0) {
            float t = 0.f;
            #pragma unroll
            for (int j = 0; j < 8; j++) t += tile[j][oi];
            g_pwn[b * OO + o] = 1.f / fmaxf(sqrtf(t), 1e-12f);
        }
        return;
    }
    if (blk < NB_DWN + NB_PWN + NB_SX + NB_SW1 + NB_SW2) {
        const float* src;
        char* dst;
        int K, R;
        long pb;
        int i;
        if (blk < NB_DWN + NB_PWN + NB_SX) {
            i = (blk - NB_DWN - NB_PWN) * 256 + tid;
            src = x; dst = xph; K = DIN; R = TT; pb = PB_X;
        } else if (blk < NB_DWN + NB_PWN + NB_SX + NB_SW1) {
            i = (blk - NB_DWN - NB_PWN - NB_SX) * 256 + tid;
            src = w1_w; dst = w1ph; K = DIN; R = CH; pb = 0;
        } else {
            i = (blk - NB_DWN - NB_PWN - NB_SX - NB_SW1) * 256 + tid;
            src = w2_w; dst = w2ph; K = OO; R = DIN; pb = 0;
        }
        long e = (long)i * 4;
        long perb = (long)R * K;
        int bb = (int)(e / perb);
        long rem = e - (long)bb * perb;
        int r = (int)(rem / K), k = (int)(rem % K);
        float4 v = ((const float4*)src)[i];
        __half2 hA, hB;
        hA.x = __float2half(v.x); hA.y = __float2half(v.y);
        hB.x = __float2half(v.z); hB.y = __float2half(v.w);
        size_t off = (size_t)bb * pb + pk_off(r, k, K >> 5);
        uint2 hw;
        hw.x = *(uint32_t*)&hA; hw.y = *(uint32_t*)&hB;
        *(uint2*)(dst + off) = hw;
        return;
    }
    {
        int idx = blk - (NB_DWN + NB_PWN + NB_SX + NB_SW1 + NB_SW2);
        int b   = idx >> 10;
        int rem = idx & 1023;
        int c0  = (rem & 31) * 32;
        int r0  = (rem >> 5) * 32;
        int tx = tid & 31, ty = tid >> 5;
        const float* s = p_w + ((size_t)b * 1024 + r0) * 1024 + c0;
        #pragma unroll
        for (int i = 0; i < 32; i += 8)
            tile[ty + i][tx] = s[(size_t)(ty + i) * 1024 + tx];
        __syncthreads();
        #pragma unroll
        for (int i = 0; i < 32; i += 8) {
            float v = tile[tx][ty + i];
            size_t off = (size_t)b * PB_1K + pk_off(c0 + ty + i, r0 + tx, 32);
            *(__half*)(pTph + off) = __float2half(v);
        }
    }
}

// ---------------------------------------------------------------------------
// Fused: depthwise conv (fp16 input) + transpose + fp16 quantize, packed out
// ---------------------------------------------------------------------------
__global__ void __launch_bounds__(256)
convT_kernel(const float* __restrict__ d_w, const float* __restrict__ d_g,
             const float* __restrict__ d_b, const float* __restrict__ p_g,
             char* __restrict__ hi) {
    __shared__ float tile[32][41];
    int b = blockIdx.z, c0 = blockIdx.y * 32, t0 = blockIdx.x * 32;
    int tid = threadIdx.y * 32 + threadIdx.x;

    const __half* hbase = g_h + ((size_t)b * CH + c0) * TT;
    #pragma unroll
    for (int i = tid; i < 32 * 40; i += 256) {
        int c = i / 40, j = i % 40;
        int t = t0 - 4 + j;
        tile[c][j] = (t >= 0 && t < TT)
                     ? __half2float(hbase[(size_t)c * TT + t]) : 0.f;
    }
    __syncthreads();

    int tx = threadIdx.x;
    int c  = c0 + tx;
    float gg   = d_g[b * CH + c];
    float pg   = p_g[b * CH + c];
    float bias = d_b[b * CH + c];
    float w[KW];
    #pragma unroll
    for (int k = 0; k < KW; k++)
        w[k] = d_w[((size_t)b * CH + c) * KW + k] * g_dwn[b * KW + k] * gg;

    #pragma unroll
    for (int i = 0; i < 4; i++) {
        int tl = threadIdx.y + i * 8;
        float acc = bias;
        #pragma unroll
        for (int k = 0; k < KW; k++) acc = fmaf(tile[tx][tl + k], w[k], acc);
        float v = acc * pg;
        size_t off = (size_t)b * PB_1K + pk_off(t0 + tl, c, 32);
        *(__half*)(hi + off) = __float2half(v);
    }
}

// ---------------------------------------------------------------------------
// PTX helpers
// ---------------------------------------------------------------------------
__device__ __forceinline__ uint32_t smem_u32(const void* p) {
    uint32_t a;
    asm("{ .reg .u64 t; cvta.to.shared.u64 t, %1; cvt.u32.u64 %0, t; }"
        : "=r"(a) : "l"(p));
    return a;
}

__device__ __forceinline__ void mbar_init(uint32_t m, uint32_t cnt) {
    asm volatile("mbarrier.init.shared.b64 [%0], %1;" :: "r"(m), "r"(cnt)
                 : "memory");
}

__device__ __forceinline__ void mbar_expect(uint32_t m, uint32_t tx) {
    asm volatile("mbarrier.arrive.expect_tx.shared.b64 _, [%0], %1;"
                 :: "r"(m), "r"(tx) : "memory");
}

__device__ __forceinline__ void mbar_arrive(uint32_t m) {
    asm volatile("mbarrier.arrive.shared.b64 _, [%0];" :: "r"(m) : "memory");
}

__device__ __forceinline__ void bulk_g2s(uint32_t dst, const void* src,
                                         uint32_t bytes, uint32_t mbar) {
    asm volatile(
        "cp.async.bulk.shared::cluster.global.mbarrier::complete_tx::bytes "
        "[%0], [%1], %2, [%3];"
        :: "r"(dst), "l"(src), "r"(bytes), "r"(mbar) : "memory");
}

__device__ __forceinline__ void mbar_wait(uint32_t m, uint32_t parity) {
    uint32_t done = 0;
    while (!done)
        asm volatile(
            "{ .reg .pred P; mbarrier.try_wait.parity.shared.b64 P, [%1], %2; "
            "selp.b32 %0,1,0,P; }"
            : "=r"(done) : "r"(m), "r"(parity) : "memory");
}

__device__ __forceinline__ void ldsm4(uint32_t* r, uint32_t a) {
    asm volatile("ldmatrix.sync.aligned.m8n8.x4.shared.b16 {%0,%1,%2,%3}, [%4];"
                 : "=r"(r[0]), "=r"(r[1]), "=r"(r[2]), "=r"(r[3]) : "r"(a));
}

__device__ __forceinline__ void ldsm2(uint32_t* r, uint32_t a) {
    asm volatile("ldmatrix.sync.aligned.m8n8.x2.shared.b16 {%0,%1}, [%2];"
                 : "=r"(r[0]), "=r"(r[1]) : "r"(a));
}

__device__ __forceinline__ void mma16816(float* d, const uint32_t* a,
                                         const uint32_t* b) {
    asm volatile(
        "mma.sync.aligned.m16n8k16.row.col.f32.f16.f16.f32 "
        "{%0,%1,%2,%3}, {%4,%5,%6,%7}, {%8,%9}, {%0,%1,%2,%3};"
        : "+f"(d[0]), "+f"(d[1]), "+f"(d[2]), "+f"(d[3])
        : "r"(a[0]), "r"(a[1]), "r"(a[2]), "r"(a[3]), "r"(b[0]), "r"(b[1]));
}

// ---------------------------------------------------------------------------
// Single-pass fp16 GEMM, producer-consumer pipeline (R10 compute path).
// Template NJ = j-tiles per warp (each 8 wide): CTA tile = 128 x (32*NJ).
//   NJ=4 -> 128x128 (GEMM1/2), NJ=2 -> 128x64 (GEMM3, 2x CTAs for wave fill).
// B fragments via ldsm2 (conflict-free on the 80B-padded panel).
// EPI 1: fp16 C = mish(v + e1[m])
// EPI 2: packed fp16 C = v*e1[b*OO+n] + e2[b*OO+n]
// EPI 3: fp32 C = v + e1[n] + e2[b][m][n]
// ---------------------------------------------------------------------------
#define ASEG  SEGB                       // A: 128 rows
#define NSTG  4

template<int EPI, int NJ>
__global__ void __launch_bounds__(256, 2)
mma_gemm(const char* __restrict__ Ah, long sA,
         const char* __restrict__ Bh, long sB,
         void* __restrict__ C0, long sC,
         int M, int N, int K,
         const float* __restrict__ e1, const float* __restrict__ e2)
{
    constexpr int BN   = 32 * NJ;        // CTA n-tile
    constexpr int BSEG = BN * PROWB;     // B stage bytes
    constexpr int STG  = ASEG + BSEG;

    extern __shared__ __align__(128) char sm[];
    const uint32_t smb = smem_u32(sm);
    const uint32_t mbF = smb + NSTG * STG;
    const uint32_t mbE = mbF + NSTG * 8;
    const int tid = threadIdx.x, lane = tid & 31, wid = tid >> 5;
    const int b = blockIdx.z;
    const int m0 = blockIdx.y * 128, n0 = blockIdx.x * BN;
    const int wm = wid >> 2, wn = wid & 3;
    const int nk = K >> 5;

    const char* pAh = Ah + (size_t)b * sA + (size_t)(m0 >> 7) * nk * SEGB;
    const char* pBh = Bh + (size_t)b * sB + (size_t)(n0 >> 7) * nk * SEGB
                         + (size_t)(n0 & 127) * PROWB;

    if (tid < NSTG) {
        mbar_init(mbF + tid * 8, 1);
        mbar_init(mbE + tid * 8, 8);
    }
    __syncthreads();

    float acc[4][NJ][4];
    #pragma unroll
    for (int i = 0; i < 4; i++)
        #pragma unroll
        for (int j = 0; j < NJ; j++)
            #pragma unroll
            for (int r = 0; r < 4; r++) acc[i][j][r] = 0.f;

    auto issue = [&](int kc) {
        int s = kc & (NSTG - 1);
        uint32_t mb = mbF + s * 8;
        uint32_t sb = smb + s * STG;
        size_t go = (size_t)kc * SEGB;
        mbar_expect(mb, STG);
        bulk_g2s(sb,        pAh + go, ASEG, mb);
        bulk_g2s(sb + ASEG, pBh + go, BSEG, mb);
    };

    auto compute = [&](int s) {
        const uint32_t sb = smb + s * STG;
        #pragma unroll
        for (int ks = 0; ks < 2; ks++) {
            uint32_t ah[4][4], bh[NJ][2];
            #pragma unroll
            for (int i = 0; i < 4; i++) {
                uint32_t ad = sb +
                    (uint32_t)((wm * 64 + i * 16 + (lane & 15)) * PROWB) +
                    ks * 32 + (lane >> 4) * 16;
                ldsm4(ah[i], ad);
            }
            #pragma unroll
            for (int j = 0; j < NJ; j++) {
                uint32_t bd = sb + ASEG +
                    (uint32_t)((wn * (BN / 4) + j * 8 + (lane & 7)) * PROWB) +
                    ks * 32 + ((lane >> 3) & 1) * 16;
                ldsm2(bh[j], bd);
            }
            #pragma unroll
            for (int i = 0; i < 4; i++)
                #pragma unroll
                for (int j = 0; j < NJ; j++)
                    mma16816(acc[i][j], ah[i], bh[j]);
        }
    };

    if (tid == 0) {
        #pragma unroll
        for (int p = 0; p < NSTG - 1; p++)
            if (p < nk) issue(p);
    }
    for (int kc = 0; kc < nk; kc++) {
        int s = kc & (NSTG - 1);
        mbar_wait(mbF + s * 8, (kc >> 2) & 1);
        compute(s);
        if (lane == 0) mbar_arrive(mbE + s * 8);
        int kn = kc + NSTG - 1;
        if (kn < nk && tid == 0) {
            int sn = kn & (NSTG - 1);
            if (kn >= NSTG)
                mbar_wait(mbE + sn * 8, ((kn - NSTG) >> 2) & 1);
            issue(kn);
        }
    }

    // --- epilogue ---
    const float* E1 = e1;
    const float* E2 = e2;
    if (EPI == 2) { E1 = e1 + b * OO; E2 = e2 + b * OO; }
    if (EPI == 3) { E2 = e2 + (size_t)b * M * N; }

    char* C0b = (char*)C0 + (size_t)b * sC;

    const int mrow0 = m0 + wm * 64;
    const int ncol0 = n0 + wn * (BN / 4);
    #pragma unroll
    for (int i = 0; i < 4; i++) {
        #pragma unroll
        for (int r = 0; r < 2; r++) {
            int m = mrow0 + i * 16 + (lane >> 2) + r * 8;
            #pragma unroll
            for (int j = 0; j < NJ; j++) {
                int n = ncol0 + j * 8 + (lane & 3) * 2;
                float v0 = acc[i][j][r * 2 + 0];
                float v1 = acc[i][j][r * 2 + 1];
                size_t off = (size_t)m * N + n;
                if (EPI == 1) {
                    float bb = E1[m];
                    __half2 hv;
                    hv.x = __float2half(mishf(v0 + bb));
                    hv.y = __float2half(mishf(v1 + bb));
                    *(__half2*)((__half*)C0b + off) = hv;
                } else if (EPI == 2) {
                    v0 = v0 * E1[n] + E2[n];
                    v1 = v1 * E1[n + 1] + E2[n + 1];
                    __half2 hv;
                    hv.x = __float2half(v0);
                    hv.y = __float2half(v1);
                    size_t po = pk_off(m, n, N >> 5);
                    *(uint32_t*)(C0b + po) = *(uint32_t*)&hv;
                } else {
                    float2 o;
                    o.x = v0 + E1[n]     + E2[off];
                    o.y = v1 + E1[n + 1] + E2[off + 1];
                    *(float2*)((float*)C0b + off) = o;
                }
            }
        }
    }
}

#define SMEM_OF(NJ_) (NSTG * (ASEG + 32 * (NJ_) * PROWB) + 2 * NSTG * 8)

// ---------------------------------------------------------------------------
extern "C" void kernel_launch(void* const* d_in, const int* in_sizes, int n_in,
                              void* d_out, int out_size) {
    const float* x    = (const float*)d_in[0];
    const float* d_w  = (const float*)d_in[1];
    const float* d_g  = (const float*)d_in[2];
    const float* d_b  = (const float*)d_in[3];
    const float* p_w  = (const float*)d_in[4];
    const float* p_g  = (const float*)d_in[5];
    const float* p_b  = (const float*)d_in[6];
    const float* w1_w = (const float*)d_in[7];
    const float* w1_b = (const float*)d_in[8];
    const float* w2_w = (const float*)d_in[9];
    const float* w2_b = (const float*)d_in[10];
    float* out = (float*)d_out;

    void *p_gh, *p_gpwn;
    void *p_xh, *p_w1h, *p_w2h, *p_pth, *p_yth, *p_y2h;
    cudaGetSymbolAddress(&p_gh,   g_h);
    cudaGetSymbolAddress(&p_gpwn, g_pwn);
    cudaGetSymbolAddress(&p_xh,   g_xph);
    cudaGetSymbolAddress(&p_w1h,  g_w1ph);
    cudaGetSymbolAddress(&p_w2h,  g_w2ph);
    cudaGetSymbolAddress(&p_pth,  g_pTph);
    cudaGetSymbolAddress(&p_yth,  g_yTph);
    cudaGetSymbolAddress(&p_y2h,  g_y2ph);
    float* gpwn = (float*)p_gpwn;

    cudaFuncSetAttribute((const void*)mma_gemm<1, 4>,
                         cudaFuncAttributeMaxDynamicSharedMemorySize,
                         SMEM_OF(4));
    cudaFuncSetAttribute((const void*)mma_gemm<2, 4>,
                         cudaFuncAttributeMaxDynamicSharedMemorySize,
                         SMEM_OF(4));
    cudaFuncSetAttribute((const void*)mma_gemm<3, 2>,
                         cudaFuncAttributeMaxDynamicSharedMemorySize,
                         SMEM_OF(2));

    // 1) fused preprocessing (norms + all input conversions), one launch
    prep_kernel<<<NB_TOT, 256>>>(x, d_w, p_w, w1_w, w2_w,
                                 (char*)p_xh, (char*)p_w1h,
                                 (char*)p_w2h, (char*)p_pth);

    // 2) GEMM1: h = mish(w1 . x + w1_b)   M=CH, N=TT, K=DIN  (fp16 out)
    {
        dim3 grid(TT / 128, CH / 128, BB);
        mma_gemm<1, 4><<<grid, 256, SMEM_OF(4)>>>(
            (char*)p_w1h, 0L,
            (char*)p_xh, (long)PB_X,
            p_gh, (long)CH * TT * 2,
            CH, TT, DIN, w1_b, nullptr);
    }

    // 3) fused conv + transpose + fp16 quantize -> yT packed
    {
        dim3 grid(TT / 32, CH / 32, BB);
        convT_kernel<<<grid, dim3(32, 8)>>>(d_w, d_g, d_b, p_g, (char*)p_yth);
    }

    // 4) GEMM2: y2 = (yT . pT)*pwn + p_b   M=TT, N=OO, K=CH  (packed fp16 out)
    {
        dim3 grid(OO / 128, TT / 128, BB);
        mma_gemm<2, 4><<<grid, 256, SMEM_OF(4)>>>(
            (char*)p_yth, (long)PB_1K,
            (char*)p_pth, (long)PB_1K,
            p_y2h, (long)PB_1K,
            TT, OO, CH, gpwn, p_b);
    }

    // 5) GEMM3: out = y2 . w2^T + w2_b + x   M=TT, N=DIN, K=OO
    //    128x64 CTA tiles -> 256 CTAs (fills the 296 co-residency slots)
    {
        dim3 grid(DIN / 64, TT / 128, BB);
        mma_gemm<3, 2><<<grid, 256, SMEM_OF(2)>>>(
            (char*)p_y2h, (long)PB_1K,
            (char*)p_w2h, 0L,
            out, (long)TT * DIN * 4,
            TT, DIN, OO, w2_b, x);
    }
}

// round 13
// speedup vs baseline: 1.0957x; 1.0171x over previous
#include <cuda_runtime.h>
#include <cuda_fp16.h>
#include <math.h>
#include <stdint.h>

// Problem constants
#define BB   8
#define TT   1024
#define DIN  256
#define CH   1024   // D_H1
#define OO   1024   // D_H2
#define KW   9

// Packed-panel format for GEMM operands (fp16, 2 bytes):
//   operand [R][K] (K-major) -> tiles of 128 rows x 32 k,
//   byte offset = ((r>>7)*nks + (k>>5))*SEGB + (r&127)*PROWB + (k&31)*2
#define PROWB 80
#define SEGB  10240                     // 128 * 80
#define PB_X   (8 * 8 * SEGB)           // per-batch packed x   [1024][256]
#define PB_1K  (8 * 32 * SEGB)          // per-batch packed [1024][1024]
#define PB_W2  (2 * 32 * SEGB)          // packed w2 [256][1024]

__device__ __forceinline__ size_t pk_off(int r, int k, int nks) {
    return (size_t)((r >> 7) * nks + (k >> 5)) * SEGB +
           (size_t)(r & 127) * PROWB + (size_t)(k & 31) * 2;
}

// Scratch (device globals — no allocation allowed)
__device__ __half g_h [BB * CH * TT];    // mish(w1(x)), [b][c][t], fp16
__device__ float g_pwn[BB * OO];
__device__ float g_dwn[BB * KW];
__device__ __align__(128) char g_xph [BB * PB_X];    // B of GEMM1
__device__ __align__(128) char g_w1ph[8 * 8 * SEGB]; // A of GEMM1
__device__ __align__(128) char g_w2ph[PB_W2];        // B of GEMM3
__device__ __align__(128) char g_pTph[BB * PB_1K];   // B of GEMM2
__device__ __align__(128) char g_yTph[BB * PB_1K];   // A of GEMM2
__device__ __align__(128) char g_y2ph[BB * PB_1K];   // A of GEMM3

// Fast mish: mish(v) = v * tanh(softplus(v));
// tanh(ln(1+u)) = (u^2 + 2u) / (u^2 + 2u + 2) with u = e^v.
// ~8 SASS instr (EX2 + RCP + FMAs) vs ~60+ for the libm chain. |rel err|~1e-6.
__device__ __forceinline__ float mishf(float v) {
    if (v > 20.f) return v;              // tanh(softplus) == 1 to fp32
    float u = __expf(v);
    float w = u * (u + 2.f);
    return v * w * __frcp_rn(w + 2.f);
}

// ---------------------------------------------------------------------------
// Fused preprocessing: one launch, grid-partitioned.
// ---------------------------------------------------------------------------
#define NB_DWN 72
#define NB_PWN 256
#define NB_SX  2048
#define NB_SW1 256
#define NB_SW2 256
#define NB_TC  8192
#define NB_TOT (NB_DWN + NB_PWN + NB_SX + NB_SW1 + NB_SW2 + NB_TC)

__global__ void __launch_bounds__(256)
prep_kernel(const float* __restrict__ x,
            const float* __restrict__ d_w,
            const float* __restrict__ p_w,
            const float* __restrict__ w1_w,
            const float* __restrict__ w2_w,
            char* __restrict__ xph, char* __restrict__ w1ph,
            char* __restrict__ w2ph, char* __restrict__ pTph) {
    __shared__ float tile[32][33];
    const int blk = blockIdx.x, tid = threadIdx.x;

    if (blk < NB_DWN) {
        int b = blk / KW, k = blk % KW;
        float* red = &tile[0][0];
        float s = 0.f;
        for (int c = tid; c < CH; c += 256) {
            float v = d_w[((long)b * CH + c) * KW + k];
            s += v * v;
        }
        red[tid] = s;
        __syncthreads();
        for (int off = 128; off > 0; off >>= 1) {
            if (tid < off) red[tid] += red[tid + off];
            __syncthreads();
        }
        if (tid == 0)
            g_dwn[b * KW + k] = 1.f / fmaxf(sqrtf(red[0]), 1e-12f);
        return;
    }
    if (blk < NB_DWN + NB_PWN) {
        int idx = blk - NB_DWN;
        int b  = idx / (OO / 32);
        int o0 = (idx % (OO / 32)) * 32;
        int oi = tid & 31, cg = tid >> 5;
        int o = o0 + oi;
        float s = 0.f;
        for (int c = cg; c < CH; c += 8) {
            float v = p_w[((long)b * CH + c) * OO + o];
            s += v * v;
        }
        tile[cg][oi] = s;
        __syncthreads();
        if (cg == 0) {
            float t = 0.f;
            #pragma unroll
            for (int j = 0; j < 8; j++) t += tile[j][oi];
            g_pwn[b * OO + o] = 1.f / fmaxf(sqrtf(t), 1e-12f);
        }
        return;
    }
    if (blk < NB_DWN + NB_PWN + NB_SX + NB_SW1 + NB_SW2) {
        const float* src;
        char* dst;
        int K, R;
        long pb;
        int i;
        if (blk < NB_DWN + NB_PWN + NB_SX) {
            i = (blk - NB_DWN - NB_PWN) * 256 + tid;
            src = x; dst = xph; K = DIN; R = TT; pb = PB_X;
        } else if (blk < NB_DWN + NB_PWN + NB_SX + NB_SW1) {
            i = (blk - NB_DWN - NB_PWN - NB_SX) * 256 + tid;
            src = w1_w; dst = w1ph; K = DIN; R = CH; pb = 0;
        } else {
            i = (blk - NB_DWN - NB_PWN - NB_SX - NB_SW1) * 256 + tid;
            src = w2_w; dst = w2ph; K = OO; R = DIN; pb = 0;
        }
        long e = (long)i * 4;
        long perb = (long)R * K;
        int bb = (int)(e / perb);
        long rem = e - (long)bb * perb;
        int r = (int)(rem / K), k = (int)(rem % K);
        float4 v = ((const float4*)src)[i];
        __half2 hA, hB;
        hA.x = __float2half(v.x); hA.y = __float2half(v.y);
        hB.x = __float2half(v.z); hB.y = __float2half(v.w);
        size_t off = (size_t)bb * pb + pk_off(r, k, K >> 5);
        uint2 hw;
        hw.x = *(uint32_t*)&hA; hw.y = *(uint32_t*)&hB;
        *(uint2*)(dst + off) = hw;
        return;
    }
    {
        int idx = blk - (NB_DWN + NB_PWN + NB_SX + NB_SW1 + NB_SW2);
        int b   = idx >> 10;
        int rem = idx & 1023;
        int c0  = (rem & 31) * 32;
        int r0  = (rem >> 5) * 32;
        int tx = tid & 31, ty = tid >> 5;
        const float* s = p_w + ((size_t)b * 1024 + r0) * 1024 + c0;
        #pragma unroll
        for (int i = 0; i < 32; i += 8)
            tile[ty + i][tx] = s[(size_t)(ty + i) * 1024 + tx];
        __syncthreads();
        #pragma unroll
        for (int i = 0; i < 32; i += 8) {
            float v = tile[tx][ty + i];
            size_t off = (size_t)b * PB_1K + pk_off(c0 + ty + i, r0 + tx, 32);
            *(__half*)(pTph + off) = __float2half(v);
        }
    }
}

// ---------------------------------------------------------------------------
// Fused: depthwise conv (fp16 input) + transpose + fp16 quantize, packed out
// ---------------------------------------------------------------------------
__global__ void __launch_bounds__(256)
convT_kernel(const float* __restrict__ d_w, const float* __restrict__ d_g,
             const float* __restrict__ d_b, const float* __restrict__ p_g,
             char* __restrict__ hi) {
    __shared__ float tile[32][41];
    int b = blockIdx.z, c0 = blockIdx.y * 32, t0 = blockIdx.x * 32;
    int tid = threadIdx.y * 32 + threadIdx.x;

    const __half* hbase = g_h + ((size_t)b * CH + c0) * TT;
    #pragma unroll
    for (int i = tid; i < 32 * 40; i += 256) {
        int c = i / 40, j = i % 40;
        int t = t0 - 4 + j;
        tile[c][j] = (t >= 0 && t < TT)
                     ? __half2float(hbase[(size_t)c * TT + t]) : 0.f;
    }
    __syncthreads();

    int tx = threadIdx.x;
    int c  = c0 + tx;
    float gg   = d_g[b * CH + c];
    float pg   = p_g[b * CH + c];
    float bias = d_b[b * CH + c];
    float w[KW];
    #pragma unroll
    for (int k = 0; k < KW; k++)
        w[k] = d_w[((size_t)b * CH + c) * KW + k] * g_dwn[b * KW + k] * gg;

    #pragma unroll
    for (int i = 0; i < 4; i++) {
        int tl = threadIdx.y + i * 8;
        float acc = bias;
        #pragma unroll
        for (int k = 0; k < KW; k++) acc = fmaf(tile[tx][tl + k], w[k], acc);
        float v = acc * pg;
        size_t off = (size_t)b * PB_1K + pk_off(t0 + tl, c, 32);
        *(__half*)(hi + off) = __float2half(v);
    }
}

// ---------------------------------------------------------------------------
// PTX helpers
// ---------------------------------------------------------------------------
__device__ __forceinline__ uint32_t smem_u32(const void* p) {
    uint32_t a;
    asm("{ .reg .u64 t; cvta.to.shared.u64 t, %1; cvt.u32.u64 %0, t; }"
        : "=r"(a) : "l"(p));
    return a;
}

__device__ __forceinline__ void mbar_init(uint32_t m, uint32_t cnt) {
    asm volatile("mbarrier.init.shared.b64 [%0], %1;" :: "r"(m), "r"(cnt)
                 : "memory");
}

__device__ __forceinline__ void mbar_expect(uint32_t m, uint32_t tx) {
    asm volatile("mbarrier.arrive.expect_tx.shared.b64 _, [%0], %1;"
                 :: "r"(m), "r"(tx) : "memory");
}

__device__ __forceinline__ void mbar_arrive(uint32_t m) {
    asm volatile("mbarrier.arrive.shared.b64 _, [%0];" :: "r"(m) : "memory");
}

__device__ __forceinline__ void bulk_g2s(uint32_t dst, const void* src,
                                         uint32_t bytes, uint32_t mbar) {
    asm volatile(
        "cp.async.bulk.shared::cluster.global.mbarrier::complete_tx::bytes "
        "[%0], [%1], %2, [%3];"
        :: "r"(dst), "l"(src), "r"(bytes), "r"(mbar) : "memory");
}

__device__ __forceinline__ void mbar_wait(uint32_t m, uint32_t parity) {
    uint32_t done = 0;
    while (!done)
        asm volatile(
            "{ .reg .pred P; mbarrier.try_wait.parity.shared.b64 P, [%1], %2; "
            "selp.b32 %0,1,0,P; }"
            : "=r"(done) : "r"(m), "r"(parity) : "memory");
}

__device__ __forceinline__ void ldsm4(uint32_t* r, uint32_t a) {
    asm volatile("ldmatrix.sync.aligned.m8n8.x4.shared.b16 {%0,%1,%2,%3}, [%4];"
                 : "=r"(r[0]), "=r"(r[1]), "=r"(r[2]), "=r"(r[3]) : "r"(a));
}

__device__ __forceinline__ void ldsm2(uint32_t* r, uint32_t a) {
    asm volatile("ldmatrix.sync.aligned.m8n8.x2.shared.b16 {%0,%1}, [%2];"
                 : "=r"(r[0]), "=r"(r[1]) : "r"(a));
}

__device__ __forceinline__ void mma16816(float* d, const uint32_t* a,
                                         const uint32_t* b) {
    asm volatile(
        "mma.sync.aligned.m16n8k16.row.col.f32.f16.f16.f32 "
        "{%0,%1,%2,%3}, {%4,%5,%6,%7}, {%8,%9}, {%0,%1,%2,%3};"
        : "+f"(d[0]), "+f"(d[1]), "+f"(d[2]), "+f"(d[3])
        : "r"(a[0]), "r"(a[1]), "r"(a[2]), "r"(a[3]), "r"(b[0]), "r"(b[1]));
}

// ---------------------------------------------------------------------------
// Single-pass fp16 GEMM, producer-consumer pipeline (R10/R12 compute path).
// Template NJ = j-tiles per warp (each 8 wide): CTA tile = 128 x (32*NJ).
//   NJ=4 -> 128x128 (GEMM1/2), NJ=2 -> 128x64 (GEMM3).
// B fragments via ldsm2 (conflict-free on the 80B-padded panel).
// EPI 1: fp16 C = mish(v + e1[m])        (fast mish)
// EPI 2: packed fp16 C = v*e1[b*OO+n] + e2[b*OO+n]
// EPI 3: fp32 C = v + e1[n] + e2[b][m][n]
// ---------------------------------------------------------------------------
#define ASEG  SEGB                       // A: 128 rows
#define NSTG  4

template<int EPI, int NJ>
__global__ void __launch_bounds__(256, 2)
mma_gemm(const char* __restrict__ Ah, long sA,
         const char* __restrict__ Bh, long sB,
         void* __restrict__ C0, long sC,
         int M, int N, int K,
         const float* __restrict__ e1, const float* __restrict__ e2)
{
    constexpr int BN   = 32 * NJ;        // CTA n-tile
    constexpr int BSEG = BN * PROWB;     // B stage bytes
    constexpr int STG  = ASEG + BSEG;

    extern __shared__ __align__(128) char sm[];
    const uint32_t smb = smem_u32(sm);
    const uint32_t mbF = smb + NSTG * STG;
    const uint32_t mbE = mbF + NSTG * 8;
    const int tid = threadIdx.x, lane = tid & 31, wid = tid >> 5;
    const int b = blockIdx.z;
    const int m0 = blockIdx.y * 128, n0 = blockIdx.x * BN;
    const int wm = wid >> 2, wn = wid & 3;
    const int nk = K >> 5;

    const char* pAh = Ah + (size_t)b * sA + (size_t)(m0 >> 7) * nk * SEGB;
    const char* pBh = Bh + (size_t)b * sB + (size_t)(n0 >> 7) * nk * SEGB
                         + (size_t)(n0 & 127) * PROWB;

    if (tid < NSTG) {
        mbar_init(mbF + tid * 8, 1);
        mbar_init(mbE + tid * 8, 8);
    }
    __syncthreads();

    float acc[4][NJ][4];
    #pragma unroll
    for (int i = 0; i < 4; i++)
        #pragma unroll
        for (int j = 0; j < NJ; j++)
            #pragma unroll
            for (int r = 0; r < 4; r++) acc[i][j][r] = 0.f;

    auto issue = [&](int kc) {
        int s = kc & (NSTG - 1);
        uint32_t mb = mbF + s * 8;
        uint32_t sb = smb + s * STG;
        size_t go = (size_t)kc * SEGB;
        mbar_expect(mb, STG);
        bulk_g2s(sb,        pAh + go, ASEG, mb);
        bulk_g2s(sb + ASEG, pBh + go, BSEG, mb);
    };

    auto compute = [&](int s) {
        const uint32_t sb = smb + s * STG;
        #pragma unroll
        for (int ks = 0; ks < 2; ks++) {
            uint32_t ah[4][4], bh[NJ][2];
            #pragma unroll
            for (int i = 0; i < 4; i++) {
                uint32_t ad = sb +
                    (uint32_t)((wm * 64 + i * 16 + (lane & 15)) * PROWB) +
                    ks * 32 + (lane >> 4) * 16;
                ldsm4(ah[i], ad);
            }
            #pragma unroll
            for (int j = 0; j < NJ; j++) {
                uint32_t bd = sb + ASEG +
                    (uint32_t)((wn * (BN / 4) + j * 8 + (lane & 7)) * PROWB) +
                    ks * 32 + ((lane >> 3) & 1) * 16;
                ldsm2(bh[j], bd);
            }
            #pragma unroll
            for (int i = 0; i < 4; i++)
                #pragma unroll
                for (int j = 0; j < NJ; j++)
                    mma16816(acc[i][j], ah[i], bh[j]);
        }
    };

    if (tid == 0) {
        #pragma unroll
        for (int p = 0; p < NSTG - 1; p++)
            if (p < nk) issue(p);
    }
    for (int kc = 0; kc < nk; kc++) {
        int s = kc & (NSTG - 1);
        mbar_wait(mbF + s * 8, (kc >> 2) & 1);
        compute(s);
        if (lane == 0) mbar_arrive(mbE + s * 8);
        int kn = kc + NSTG - 1;
        if (kn < nk && tid == 0) {
            int sn = kn & (NSTG - 1);
            if (kn >= NSTG)
                mbar_wait(mbE + sn * 8, ((kn - NSTG) >> 2) & 1);
            issue(kn);
        }
    }

    // --- epilogue ---
    const float* E1 = e1;
    const float* E2 = e2;
    if (EPI == 2) { E1 = e1 + b * OO; E2 = e2 + b * OO; }
    if (EPI == 3) { E2 = e2 + (size_t)b * M * N; }

    char* C0b = (char*)C0 + (size_t)b * sC;

    const int mrow0 = m0 + wm * 64;
    const int ncol0 = n0 + wn * (BN / 4);
    #pragma unroll
    for (int i = 0; i < 4; i++) {
        #pragma unroll
        for (int r = 0; r < 2; r++) {
            int m = mrow0 + i * 16 + (lane >> 2) + r * 8;
            #pragma unroll
            for (int j = 0; j < NJ; j++) {
                int n = ncol0 + j * 8 + (lane & 3) * 2;
                float v0 = acc[i][j][r * 2 + 0];
                float v1 = acc[i][j][r * 2 + 1];
                size_t off = (size_t)m * N + n;
                if (EPI == 1) {
                    float bb = E1[m];
                    __half2 hv;
                    hv.x = __float2half(mishf(v0 + bb));
                    hv.y = __float2half(mishf(v1 + bb));
                    *(__half2*)((__half*)C0b + off) = hv;
                } else if (EPI == 2) {
                    v0 = v0 * E1[n] + E2[n];
                    v1 = v1 * E1[n + 1] + E2[n + 1];
                    __half2 hv;
                    hv.x = __float2half(v0);
                    hv.y = __float2half(v1);
                    size_t po = pk_off(m, n, N >> 5);
                    *(uint32_t*)(C0b + po) = *(uint32_t*)&hv;
                } else {
                    float2 o;
                    o.x = v0 + E1[n]     + E2[off];
                    o.y = v1 + E1[n + 1] + E2[off + 1];
                    *(float2*)((float*)C0b + off) = o;
                }
            }
        }
    }
}

#define SMEM_OF(NJ_) (NSTG * (ASEG + 32 * (NJ_) * PROWB) + 2 * NSTG * 8)

// ---------------------------------------------------------------------------
extern "C" void kernel_launch(void* const* d_in, const int* in_sizes, int n_in,
                              void* d_out, int out_size) {
    const float* x    = (const float*)d_in[0];
    const float* d_w  = (const float*)d_in[1];
    const float* d_g  = (const float*)d_in[2];
    const float* d_b  = (const float*)d_in[3];
    const float* p_w  = (const float*)d_in[4];
    const float* p_g  = (const float*)d_in[5];
    const float* p_b  = (const float*)d_in[6];
    const float* w1_w = (const float*)d_in[7];
    const float* w1_b = (const float*)d_in[8];
    const float* w2_w = (const float*)d_in[9];
    const float* w2_b = (const float*)d_in[10];
    float* out = (float*)d_out;

    void *p_gh, *p_gpwn;
    void *p_xh, *p_w1h, *p_w2h, *p_pth, *p_yth, *p_y2h;
    cudaGetSymbolAddress(&p_gh,   g_h);
    cudaGetSymbolAddress(&p_gpwn, g_pwn);
    cudaGetSymbolAddress(&p_xh,   g_xph);
    cudaGetSymbolAddress(&p_w1h,  g_w1ph);
    cudaGetSymbolAddress(&p_w2h,  g_w2ph);
    cudaGetSymbolAddress(&p_pth,  g_pTph);
    cudaGetSymbolAddress(&p_yth,  g_yTph);
    cudaGetSymbolAddress(&p_y2h,  g_y2ph);
    float* gpwn = (float*)p_gpwn;

    cudaFuncSetAttribute((const void*)mma_gemm<1, 4>,
                         cudaFuncAttributeMaxDynamicSharedMemorySize,
                         SMEM_OF(4));
    cudaFuncSetAttribute((const void*)mma_gemm<2, 4>,
                         cudaFuncAttributeMaxDynamicSharedMemorySize,
                         SMEM_OF(4));
    cudaFuncSetAttribute((const void*)mma_gemm<3, 2>,
                         cudaFuncAttributeMaxDynamicSharedMemorySize,
                         SMEM_OF(2));

    // 1) fused preprocessing (norms + all input conversions), one launch
    prep_kernel<<<NB_TOT, 256>>>(x, d_w, p_w, w1_w, w2_w,
                                 (char*)p_xh, (char*)p_w1h,
                                 (char*)p_w2h, (char*)p_pth);

    // 2) GEMM1: h = mish(w1 . x + w1_b)   M=CH, N=TT, K=DIN  (fp16 out)
    {
        dim3 grid(TT / 128, CH / 128, BB);
        mma_gemm<1, 4><<<grid, 256, SMEM_OF(4)>>>(
            (char*)p_w1h, 0L,
            (char*)p_xh, (long)PB_X,
            p_gh, (long)CH * TT * 2,
            CH, TT, DIN, w1_b, nullptr);
    }

    // 3) fused conv + transpose + fp16 quantize -> yT packed
    {
        dim3 grid(TT / 32, CH / 32, BB);
        convT_kernel<<<grid, dim3(32, 8)>>>(d_w, d_g, d_b, p_g, (char*)p_yth);
    }

    // 4) GEMM2: y2 = (yT . pT)*pwn + p_b   M=TT, N=OO, K=CH  (packed fp16 out)
    {
        dim3 grid(OO / 128, TT / 128, BB);
        mma_gemm<2, 4><<<grid, 256, SMEM_OF(4)>>>(
            (char*)p_yth, (long)PB_1K,
            (char*)p_pth, (long)PB_1K,
            p_y2h, (long)PB_1K,
            TT, OO, CH, gpwn, p_b);
    }

    // 5) GEMM3: out = y2 . w2^T + w2_b + x   M=TT, N=DIN, K=OO
    {
        dim3 grid(DIN / 64, TT / 128, BB);
        mma_gemm<3, 2><<<grid, 256, SMEM_OF(2)>>>(
            (char*)p_y2h, (long)PB_1K,
            (char*)p_w2h, 0L,
            out, (long)TT * DIN * 4,
            TT, DIN, OO, w2_b, x);
    }
}

// round 14
// speedup vs baseline: 1.1066x; 1.0100x over previous
#include <cuda_runtime.h>
#include <cuda_fp16.h>
#include <math.h>
#include <stdint.h>

// Problem constants
#define BB   8
#define TT   1024
#define DIN  256
#define CH   1024   // D_H1
#define OO   1024   // D_H2
#define KW   9

// Packed-panel format for GEMM operands (fp16, 2 bytes):
//   operand [R][K] (K-major) -> tiles of 128 rows x 32 k,
//   byte offset = ((r>>7)*nks + (k>>5))*SEGB + (r&127)*PROWB + (k&31)*2
#define PROWB 80
#define SEGB  10240                     // 128 * 80
#define PB_X   (8 * 8 * SEGB)           // per-batch packed x   [1024][256]
#define PB_1K  (8 * 32 * SEGB)          // per-batch packed [1024][1024]
#define PB_W2  (2 * 32 * SEGB)          // packed w2 [256][1024]

__device__ __forceinline__ size_t pk_off(int r, int k, int nks) {
    return (size_t)((r >> 7) * nks + (k >> 5)) * SEGB +
           (size_t)(r & 127) * PROWB + (size_t)(k & 31) * 2;
}

// Scratch (device globals — no allocation allowed)
__device__ __half g_h [BB * CH * TT];    // mish(w1(x)), [b][c][t], fp16
__device__ float g_pwn[BB * OO];
__device__ float g_dwn[BB * KW];
__device__ __align__(128) char g_xph [BB * PB_X];    // B of GEMM1
__device__ __align__(128) char g_w1ph[8 * 8 * SEGB]; // A of GEMM1
__device__ __align__(128) char g_w2ph[PB_W2];        // B of GEMM3
__device__ __align__(128) char g_pTph[BB * PB_1K];   // B of GEMM2
__device__ __align__(128) char g_yTph[BB * PB_1K];   // A of GEMM2
__device__ __align__(128) char g_y2ph[BB * PB_1K];   // A of GEMM3

// Fast mish: mish(v) = v * tanh(softplus(v));
// tanh(ln(1+u)) = (u^2 + 2u) / (u^2 + 2u + 2) with u = e^v.
__device__ __forceinline__ float mishf(float v) {
    if (v > 20.f) return v;
    float u = __expf(v);
    float w = u * (u + 2.f);
    return v * w * __frcp_rn(w + 2.f);
}

// ---------------------------------------------------------------------------
// Fused preprocessing: one launch, grid-partitioned.
// ---------------------------------------------------------------------------
#define NB_DWN 72
#define NB_PWN 256
#define NB_SX  2048
#define NB_SW1 256
#define NB_SW2 256
#define NB_TC  8192
#define NB_TOT (NB_DWN + NB_PWN + NB_SX + NB_SW1 + NB_SW2 + NB_TC)

__global__ void __launch_bounds__(256)
prep_kernel(const float* __restrict__ x,
            const float* __restrict__ d_w,
            const float* __restrict__ p_w,
            const float* __restrict__ w1_w,
            const float* __restrict__ w2_w,
            char* __restrict__ xph, char* __restrict__ w1ph,
            char* __restrict__ w2ph, char* __restrict__ pTph) {
    __shared__ float tile[32][33];
    const int blk = blockIdx.x, tid = threadIdx.x;

    if (blk < NB_DWN) {
        int b = blk / KW, k = blk % KW;
        float* red = &tile[0][0];
        float s = 0.f;
        for (int c = tid; c < CH; c += 256) {
            float v = d_w[((long)b * CH + c) * KW + k];
            s += v * v;
        }
        red[tid] = s;
        __syncthreads();
        for (int off = 128; off > 0; off >>= 1) {
            if (tid < off) red[tid] += red[tid + off];
            __syncthreads();
        }
        if (tid == 0)
            g_dwn[b * KW + k] = 1.f / fmaxf(sqrtf(red[0]), 1e-12f);
        return;
    }
    if (blk < NB_DWN + NB_PWN) {
        int idx = blk - NB_DWN;
        int b  = idx / (OO / 32);
        int o0 = (idx % (OO / 32)) * 32;
        int oi = tid & 31, cg = tid >> 5;
        int o = o0 + oi;
        float s = 0.f;
        for (int c = cg; c < CH; c += 8) {
            float v = p_w[((long)b * CH + c) * OO + o];
            s += v * v;
        }
        tile[cg][oi] = s;
        __syncthreads();
        if (cg == 0) {
            float t = 0.f;
            #pragma unroll
            for (int j = 0; j < 8; j++) t += tile[j][oi];
            g_pwn[b * OO + o] = 1.f / fmaxf(sqrtf(t), 1e-12f);
        }
        return;
    }
    if (blk < NB_DWN + NB_PWN + NB_SX + NB_SW1 + NB_SW2) {
        const float* src;
        char* dst;
        int K, R;
        long pb;
        int i;
        if (blk < NB_DWN + NB_PWN + NB_SX) {
            i = (blk - NB_DWN - NB_PWN) * 256 + tid;
            src = x; dst = xph; K = DIN; R = TT; pb = PB_X;
        } else if (blk < NB_DWN + NB_PWN + NB_SX + NB_SW1) {
            i = (blk - NB_DWN - NB_PWN - NB_SX) * 256 + tid;
            src = w1_w; dst = w1ph; K = DIN; R = CH; pb = 0;
        } else {
            i = (blk - NB_DWN - NB_PWN - NB_SX - NB_SW1) * 256 + tid;
            src = w2_w; dst = w2ph; K = OO; R = DIN; pb = 0;
        }
        long e = (long)i * 4;
        long perb = (long)R * K;
        int bb = (int)(e / perb);
        long rem = e - (long)bb * perb;
        int r = (int)(rem / K), k = (int)(rem % K);
        float4 v = ((const float4*)src)[i];
        __half2 hA, hB;
        hA.x = __float2half(v.x); hA.y = __float2half(v.y);
        hB.x = __float2half(v.z); hB.y = __float2half(v.w);
        size_t off = (size_t)bb * pb + pk_off(r, k, K >> 5);
        uint2 hw;
        hw.x = *(uint32_t*)&hA; hw.y = *(uint32_t*)&hB;
        *(uint2*)(dst + off) = hw;
        return;
    }
    {
        // transpose + quantize p_w -> pTph, half2 stores (c-pair per thread)
        int idx = blk - (NB_DWN + NB_PWN + NB_SX + NB_SW1 + NB_SW2);
        int b   = idx >> 10;
        int rem = idx & 1023;
        int c0  = (rem & 31) * 32;
        int r0  = (rem >> 5) * 32;
        int tx = tid & 31, ty = tid >> 5;
        const float* s = p_w + ((size_t)b * 1024 + r0) * 1024 + c0;
        #pragma unroll
        for (int i = 0; i < 32; i += 8)
            tile[ty + i][tx] = s[(size_t)(ty + i) * 1024 + tx];
        __syncthreads();
        int kp = tid & 15, rr0 = tid >> 4;    // 16 k-pairs x 16 rows
        #pragma unroll
        for (int it = 0; it < 2; it++) {
            int rr = rr0 + it * 16;
            __half2 hv;
            hv.x = __float2half(tile[2 * kp][rr]);
            hv.y = __float2half(tile[2 * kp + 1][rr]);
            size_t off = (size_t)b * PB_1K + pk_off(c0 + rr, r0 + 2 * kp, 32);
            *(__half2*)(pTph + off) = hv;
        }
    }
}

// ---------------------------------------------------------------------------
// Fused: depthwise conv (fp16 input) + transpose + fp16 quantize, packed out
// Vectorized: uint2 (4xfp16) loads, half2 stores (c-pair per thread).
// Grid (TT/32, CH/32, BB), flat block 256.
// ---------------------------------------------------------------------------
__global__ void __launch_bounds__(256)
convT_kernel(const float* __restrict__ d_w, const float* __restrict__ d_g,
             const float* __restrict__ d_b, const float* __restrict__ p_g,
             char* __restrict__ hi) {
    __shared__ float tile[32][41];       // [c][j], j = t - (t0-4), 0..39
    int b = blockIdx.z, c0 = blockIdx.y * 32, t0 = blockIdx.x * 32;
    int tid = threadIdx.x;

    const __half* hbase = g_h + ((size_t)b * CH + c0) * TT;
    // 32 rows x 10 quads of 4 fp16
    #pragma unroll
    for (int i = tid; i < 320; i += 256) {
        int c = i / 10, q = i - c * 10;
        int t = t0 - 4 + q * 4;
        if (t >= 0 && t + 3 < TT) {
            uint2 u = *(const uint2*)(hbase + (size_t)c * TT + t);
            __half2 p0 = *(__half2*)&u.x, p1 = *(__half2*)&u.y;
            tile[c][q * 4 + 0] = __half2float(p0.x);
            tile[c][q * 4 + 1] = __half2float(p0.y);
            tile[c][q * 4 + 2] = __half2float(p1.x);
            tile[c][q * 4 + 3] = __half2float(p1.y);
        } else {
            #pragma unroll
            for (int e = 0; e < 4; e++) {
                int tt = t + e;
                tile[c][q * 4 + e] = (tt >= 0 && tt < TT)
                    ? __half2float(hbase[(size_t)c * TT + tt]) : 0.f;
            }
        }
    }
    __syncthreads();

    int kp = tid & 15, tr = tid >> 4;    // c-pair, t-row group
    int ca = c0 + 2 * kp;
    float ga = d_g[b * CH + ca],     gb = d_g[b * CH + ca + 1];
    float pa = p_g[b * CH + ca],     pb = p_g[b * CH + ca + 1];
    float b0 = d_b[b * CH + ca],     b1 = d_b[b * CH + ca + 1];
    float wa[KW], wb[KW];
    #pragma unroll
    for (int k = 0; k < KW; k++) {
        float dn = g_dwn[b * KW + k];
        wa[k] = d_w[((size_t)b * CH + ca) * KW + k]     * dn * ga;
        wb[k] = d_w[((size_t)b * CH + ca + 1) * KW + k] * dn * gb;
    }

    #pragma unroll
    for (int it = 0; it < 2; it++) {
        int tl = tr + it * 16;
        float a0 = b0, a1 = b1;
        #pragma unroll
        for (int k = 0; k < KW; k++) {
            a0 = fmaf(tile[2 * kp][tl + k],     wa[k], a0);
            a1 = fmaf(tile[2 * kp + 1][tl + k], wb[k], a1);
        }
        __half2 hv;
        hv.x = __float2half(a0 * pa);
        hv.y = __float2half(a1 * pb);
        size_t off = (size_t)b * PB_1K + pk_off(t0 + tl, ca, 32);
        *(__half2*)(hi + off) = hv;
    }
}

// ---------------------------------------------------------------------------
// PTX helpers
// ---------------------------------------------------------------------------
__device__ __forceinline__ uint32_t smem_u32(const void* p) {
    uint32_t a;
    asm("{ .reg .u64 t; cvta.to.shared.u64 t, %1; cvt.u32.u64 %0, t; }"
        : "=r"(a) : "l"(p));
    return a;
}

__device__ __forceinline__ void mbar_init(uint32_t m, uint32_t cnt) {
    asm volatile("mbarrier.init.shared.b64 [%0], %1;" :: "r"(m), "r"(cnt)
                 : "memory");
}

__device__ __forceinline__ void mbar_expect(uint32_t m, uint32_t tx) {
    asm volatile("mbarrier.arrive.expect_tx.shared.b64 _, [%0], %1;"
                 :: "r"(m), "r"(tx) : "memory");
}

__device__ __forceinline__ void mbar_arrive(uint32_t m) {
    asm volatile("mbarrier.arrive.shared.b64 _, [%0];" :: "r"(m) : "memory");
}

__device__ __forceinline__ void bulk_g2s(uint32_t dst, const void* src,
                                         uint32_t bytes, uint32_t mbar) {
    asm volatile(
        "cp.async.bulk.shared::cluster.global.mbarrier::complete_tx::bytes "
        "[%0], [%1], %2, [%3];"
        :: "r"(dst), "l"(src), "r"(bytes), "r"(mbar) : "memory");
}

__device__ __forceinline__ void mbar_wait(uint32_t m, uint32_t parity) {
    uint32_t done = 0;
    while (!done)
        asm volatile(
            "{ .reg .pred P; mbarrier.try_wait.parity.shared.b64 P, [%1], %2; "
            "selp.b32 %0,1,0,P; }"
            : "=r"(done) : "r"(m), "r"(parity) : "memory");
}

__device__ __forceinline__ void ldsm4(uint32_t* r, uint32_t a) {
    asm volatile("ldmatrix.sync.aligned.m8n8.x4.shared.b16 {%0,%1,%2,%3}, [%4];"
                 : "=r"(r[0]), "=r"(r[1]), "=r"(r[2]), "=r"(r[3]) : "r"(a));
}

__device__ __forceinline__ void ldsm2(uint32_t* r, uint32_t a) {
    asm volatile("ldmatrix.sync.aligned.m8n8.x2.shared.b16 {%0,%1}, [%2];"
                 : "=r"(r[0]), "=r"(r[1]) : "r"(a));
}

__device__ __forceinline__ void mma16816(float* d, const uint32_t* a,
                                         const uint32_t* b) {
    asm volatile(
        "mma.sync.aligned.m16n8k16.row.col.f32.f16.f16.f32 "
        "{%0,%1,%2,%3}, {%4,%5,%6,%7}, {%8,%9}, {%0,%1,%2,%3};"
        : "+f"(d[0]), "+f"(d[1]), "+f"(d[2]), "+f"(d[3])
        : "r"(a[0]), "r"(a[1]), "r"(a[2]), "r"(a[3]), "r"(b[0]), "r"(b[1]));
}

// ---------------------------------------------------------------------------
// Single-pass fp16 GEMM, producer-consumer pipeline.
// Template NJ = j-tiles per warp, NS = pipeline stages.
//   GEMM1/2: NJ=4, NS=4 (proven config). GEMM3: NJ=2, NS=6 (deeper pipeline
//   to cover bulk-load latency on cheap tiles).
// EPI 1: fp16 C = mish(v + e1[m])
// EPI 2: packed fp16 C = v*e1[b*OO+n] + e2[b*OO+n]
// EPI 3: fp32 C = v + e1[n] + e2[b][m][n]
// ---------------------------------------------------------------------------
#define ASEG  SEGB                       // A: 128 rows

template<int EPI, int NJ, int NS>
__global__ void __launch_bounds__(256, 2)
mma_gemm(const char* __restrict__ Ah, long sA,
         const char* __restrict__ Bh, long sB,
         void* __restrict__ C0, long sC,
         int M, int N, int K,
         const float* __restrict__ e1, const float* __restrict__ e2)
{
    constexpr int BN   = 32 * NJ;        // CTA n-tile
    constexpr int BSEG = BN * PROWB;     // B stage bytes
    constexpr int STG  = ASEG + BSEG;

    extern __shared__ __align__(128) char sm[];
    const uint32_t smb = smem_u32(sm);
    const uint32_t mbF = smb + NS * STG;
    const uint32_t mbE = mbF + NS * 8;
    const int tid = threadIdx.x, lane = tid & 31, wid = tid >> 5;
    const int b = blockIdx.z;
    const int m0 = blockIdx.y * 128, n0 = blockIdx.x * BN;
    const int wm = wid >> 2, wn = wid & 3;
    const int nk = K >> 5;

    const char* pAh = Ah + (size_t)b * sA + (size_t)(m0 >> 7) * nk * SEGB;
    const char* pBh = Bh + (size_t)b * sB + (size_t)(n0 >> 7) * nk * SEGB
                         + (size_t)(n0 & 127) * PROWB;

    if (tid < NS) {
        mbar_init(mbF + tid * 8, 1);
        mbar_init(mbE + tid * 8, 8);
    }
    __syncthreads();

    float acc[4][NJ][4];
    #pragma unroll
    for (int i = 0; i < 4; i++)
        #pragma unroll
        for (int j = 0; j < NJ; j++)
            #pragma unroll
            for (int r = 0; r < 4; r++) acc[i][j][r] = 0.f;

    auto issue = [&](int kc) {
        int s = kc % NS;
        uint32_t mb = mbF + s * 8;
        uint32_t sb = smb + s * STG;
        size_t go = (size_t)kc * SEGB;
        mbar_expect(mb, STG);
        bulk_g2s(sb,        pAh + go, ASEG, mb);
        bulk_g2s(sb + ASEG, pBh + go, BSEG, mb);
    };

    auto compute = [&](int s) {
        const uint32_t sb = smb + s * STG;
        #pragma unroll
        for (int ks = 0; ks < 2; ks++) {
            uint32_t ah[4][4], bh[NJ][2];
            #pragma unroll
            for (int i = 0; i < 4; i++) {
                uint32_t ad = sb +
                    (uint32_t)((wm * 64 + i * 16 + (lane & 15)) * PROWB) +
                    ks * 32 + (lane >> 4) * 16;
                ldsm4(ah[i], ad);
            }
            #pragma unroll
            for (int j = 0; j < NJ; j++) {
                uint32_t bd = sb + ASEG +
                    (uint32_t)((wn * (BN / 4) + j * 8 + (lane & 7)) * PROWB) +
                    ks * 32 + ((lane >> 3) & 1) * 16;
                ldsm2(bh[j], bd);
            }
            #pragma unroll
            for (int i = 0; i < 4; i++)
                #pragma unroll
                for (int j = 0; j < NJ; j++)
                    mma16816(acc[i][j], ah[i], bh[j]);
        }
    };

    if (tid == 0) {
        #pragma unroll
        for (int p = 0; p < NS - 1; p++)
            if (p < nk) issue(p);
    }
    for (int kc = 0; kc < nk; kc++) {
        int s = kc % NS;
        mbar_wait(mbF + s * 8, (kc / NS) & 1);
        compute(s);
        if (lane == 0) mbar_arrive(mbE + s * 8);
        int kn = kc + NS - 1;
        if (kn < nk && tid == 0) {
            int sn = kn % NS;
            if (kn >= NS)
                mbar_wait(mbE + sn * 8, (kn / NS - 1) & 1);
            issue(kn);
        }
    }

    // --- epilogue ---
    const float* E1 = e1;
    const float* E2 = e2;
    if (EPI == 2) { E1 = e1 + b * OO; E2 = e2 + b * OO; }
    if (EPI == 3) { E2 = e2 + (size_t)b * M * N; }

    char* C0b = (char*)C0 + (size_t)b * sC;

    const int mrow0 = m0 + wm * 64;
    const int ncol0 = n0 + wn * (BN / 4);
    #pragma unroll
    for (int i = 0; i < 4; i++) {
        #pragma unroll
        for (int r = 0; r < 2; r++) {
            int m = mrow0 + i * 16 + (lane >> 2) + r * 8;
            #pragma unroll
            for (int j = 0; j < NJ; j++) {
                int n = ncol0 + j * 8 + (lane & 3) * 2;
                float v0 = acc[i][j][r * 2 + 0];
                float v1 = acc[i][j][r * 2 + 1];
                size_t off = (size_t)m * N + n;
                if (EPI == 1) {
                    float bb = E1[m];
                    __half2 hv;
                    hv.x = __float2half(mishf(v0 + bb));
                    hv.y = __float2half(mishf(v1 + bb));
                    *(__half2*)((__half*)C0b + off) = hv;
                } else if (EPI == 2) {
                    v0 = v0 * E1[n] + E2[n];
                    v1 = v1 * E1[n + 1] + E2[n + 1];
                    __half2 hv;
                    hv.x = __float2half(v0);
                    hv.y = __float2half(v1);
                    size_t po = pk_off(m, n, N >> 5);
                    *(uint32_t*)(C0b + po) = *(uint32_t*)&hv;
                } else {
                    float2 o;
                    o.x = v0 + E1[n]     + E2[off];
                    o.y = v1 + E1[n + 1] + E2[off + 1];
                    *(float2*)((float*)C0b + off) = o;
                }
            }
        }
    }
}

#define SMEM_OF(NJ_, NS_) ((NS_) * (ASEG + 32 * (NJ_) * PROWB) + 2 * (NS_) * 8)

// ---------------------------------------------------------------------------
extern "C" void kernel_launch(void* const* d_in, const int* in_sizes, int n_in,
                              void* d_out, int out_size) {
    const float* x    = (const float*)d_in[0];
    const float* d_w  = (const float*)d_in[1];
    const float* d_g  = (const float*)d_in[2];
    const float* d_b  = (const float*)d_in[3];
    const float* p_w  = (const float*)d_in[4];
    const float* p_g  = (const float*)d_in[5];
    const float* p_b  = (const float*)d_in[6];
    const float* w1_w = (const float*)d_in[7];
    const float* w1_b = (const float*)d_in[8];
    const float* w2_w = (const float*)d_in[9];
    const float* w2_b = (const float*)d_in[10];
    float* out = (float*)d_out;

    void *p_gh, *p_gpwn;
    void *p_xh, *p_w1h, *p_w2h, *p_pth, *p_yth, *p_y2h;
    cudaGetSymbolAddress(&p_gh,   g_h);
    cudaGetSymbolAddress(&p_gpwn, g_pwn);
    cudaGetSymbolAddress(&p_xh,   g_xph);
    cudaGetSymbolAddress(&p_w1h,  g_w1ph);
    cudaGetSymbolAddress(&p_w2h,  g_w2ph);
    cudaGetSymbolAddress(&p_pth,  g_pTph);
    cudaGetSymbolAddress(&p_yth,  g_yTph);
    cudaGetSymbolAddress(&p_y2h,  g_y2ph);
    float* gpwn = (float*)p_gpwn;

    cudaFuncSetAttribute((const void*)mma_gemm<1, 4, 4>,
                         cudaFuncAttributeMaxDynamicSharedMemorySize,
                         SMEM_OF(4, 4));
    cudaFuncSetAttribute((const void*)mma_gemm<2, 4, 4>,
                         cudaFuncAttributeMaxDynamicSharedMemorySize,
                         SMEM_OF(4, 4));
    cudaFuncSetAttribute((const void*)mma_gemm<3, 2, 6>,
                         cudaFuncAttributeMaxDynamicSharedMemorySize,
                         SMEM_OF(2, 6));

    // 1) fused preprocessing (norms + all input conversions), one launch
    prep_kernel<<<NB_TOT, 256>>>(x, d_w, p_w, w1_w, w2_w,
                                 (char*)p_xh, (char*)p_w1h,
                                 (char*)p_w2h, (char*)p_pth);

    // 2) GEMM1: h = mish(w1 . x + w1_b)   M=CH, N=TT, K=DIN  (fp16 out)
    {
        dim3 grid(TT / 128, CH / 128, BB);
        mma_gemm<1, 4, 4><<<grid, 256, SMEM_OF(4, 4)>>>(
            (char*)p_w1h, 0L,
            (char*)p_xh, (long)PB_X,
            p_gh, (long)CH * TT * 2,
            CH, TT, DIN, w1_b, nullptr);
    }

    // 3) fused conv + transpose + fp16 quantize -> yT packed
    {
        dim3 grid(TT / 32, CH / 32, BB);
        convT_kernel<<<grid, 256>>>(d_w, d_g, d_b, p_g, (char*)p_yth);
    }

    // 4) GEMM2: y2 = (yT . pT)*pwn + p_b   M=TT, N=OO, K=CH  (packed fp16 out)
    {
        dim3 grid(OO / 128, TT / 128, BB);
        mma_gemm<2, 4, 4><<<grid, 256, SMEM_OF(4, 4)>>>(
            (char*)p_yth, (long)PB_1K,
            (char*)p_pth, (long)PB_1K,
            p_y2h, (long)PB_1K,
            TT, OO, CH, gpwn, p_b);
    }

    // 5) GEMM3: out = y2 . w2^T + w2_b + x   M=TT, N=DIN, K=OO
    {
        dim3 grid(DIN / 64, TT / 128, BB);
        mma_gemm<3, 2, 6><<<grid, 256, SMEM_OF(2, 6)>>>(
            (char*)p_y2h, (long)PB_1K,
            (char*)p_w2h, 0L,
            out, (long)TT * DIN * 4,
            TT, DIN, OO, w2_b, x);
    }
}

// round 16
// speedup vs baseline: 1.2578x; 1.1366x over previous
#include <cuda_runtime.h>
#include <cuda_fp16.h>
#include <math.h>
#include <stdint.h>

// Problem constants
#define BB   8
#define TT   1024
#define DIN  256
#define CH   1024   // D_H1
#define OO   1024   // D_H2
#define KW   9

// Packed-panel format for GEMM operands (fp16, 2 bytes):
//   operand [R][K] (K-major) -> tiles of 128 rows x 32 k,
//   byte offset = ((r>>7)*nks + (k>>5))*SEGB + (r&127)*PROWB + (k&31)*2
#define PROWB 80
#define SEGB  10240                     // 128 * 80
#define PB_X   (8 * 8 * SEGB)           // per-batch packed x   [1024][256]
#define PB_1K  (8 * 32 * SEGB)          // per-batch packed [1024][1024]
#define PB_W2  (2 * 32 * SEGB)          // packed [256][1024]

__device__ __forceinline__ size_t pk_off(int r, int k, int nks) {
    return (size_t)((r >> 7) * nks + (k >> 5)) * SEGB +
           (size_t)(r & 127) * PROWB + (size_t)(k & 31) * 2;
}

// Scratch (device globals — no allocation allowed)
__device__ __half g_h [BB * CH * TT];    // mish(w1(x)), [b][c][t], fp16
__device__ float g_pwn[BB * OO];         // 1/||p_w[b,:,o]||
__device__ float g_dwn[BB * KW];
__device__ float g_bb2[BB * DIN];        // w2_b[i] + sum_o p_b[o] w2[i][o]
__device__ __align__(128) char g_xph [BB * PB_X];    // B of GEMM1
__device__ __align__(128) char g_w1ph[8 * 8 * SEGB]; // A of GEMM1
__device__ __align__(128) char g_w2ph[PB_W2];        // A of W-GEMM [i][o]
__device__ __align__(128) char g_pAph[BB * PB_1K];   // B of W-GEMM: p_w*pwn [c][o]
__device__ __align__(128) char g_yTph[BB * PB_1K];   // A of final GEMM [t][c]
__device__ __align__(128) char g_Wtph[BB * PB_W2];   // B of final GEMM [i][c]

// Fast mish
__device__ __forceinline__ float mishf(float v) {
    if (v > 20.f) return v;
    float u = __expf(v);
    float w = u * (u + 2.f);
    return v * w * __frcp_rn(w + 2.f);
}

// ---------------------------------------------------------------------------
// Norm kernel (must precede prep: prep consumes g_pwn)
//   [0,72)   dwn   [72,328) pwn
// ---------------------------------------------------------------------------
__global__ void __launch_bounds__(256)
norm_kernel(const float* __restrict__ d_w, const float* __restrict__ p_w) {
    __shared__ float red2[8][33];
    const int blk = blockIdx.x, tid = threadIdx.x;
    if (blk < 72) {
        __shared__ float red[256];
        int b = blk / KW, k = blk % KW;
        float s = 0.f;
        for (int c = tid; c < CH; c += 256) {
            float v = d_w[((long)b * CH + c) * KW + k];
            s += v * v;
        }
        red[tid] = s;
        __syncthreads();
        for (int off = 128; off > 0; off >>= 1) {
            if (tid < off) red[tid] += red[tid + off];
            __syncthreads();
        }
        if (tid == 0)
            g_dwn[b * KW + k] = 1.f / fmaxf(sqrtf(red[0]), 1e-12f);
        return;
    }
    int idx = blk - 72;
    int b  = idx / (OO / 32);
    int o0 = (idx % (OO / 32)) * 32;
    int oi = tid & 31, cg = tid >> 5;
    int o = o0 + oi;
    float s = 0.f;
    for (int c = cg; c < CH; c += 8) {
        float v = p_w[((long)b * CH + c) * OO + o];
        s += v * v;
    }
    red2[cg][oi] = s;
    __syncthreads();
    if (cg == 0) {
        float t = 0.f;
        #pragma unroll
        for (int j = 0; j < 8; j++) t += red2[j][oi];
        g_pwn[b * OO + o] = 1.f / fmaxf(sqrtf(t), 1e-12f);
    }
}

// ---------------------------------------------------------------------------
// Fused preprocessing (after norm_kernel):
//   [0,2048)        split x   -> g_xph
//   [2048,2304)     split w1  -> g_w1ph
//   [2304,2560)     split w2  -> g_w2ph   ([i][o] K-major, natural)
//   [2560,10752)    quantize p_w[c][o]*pwn[o] -> g_pAph (no transpose!)
//   [10752,10816)   bb2[b][i] = w2_b[i] + sum_o p_b[b][o]*w2[i][o]
// ---------------------------------------------------------------------------
#define NB_SX   2048
#define NB_SW1  256
#define NB_SW2  256
#define NB_PA   8192
#define NB_BB2  64
#define NB_TOT  (NB_SX + NB_SW1 + NB_SW2 + NB_PA + NB_BB2)

__global__ void __launch_bounds__(256)
prep_kernel(const float* __restrict__ x,
            const float* __restrict__ p_w,
            const float* __restrict__ w1_w,
            const float* __restrict__ w2_w,
            const float* __restrict__ p_b,
            const float* __restrict__ w2_b,
            char* __restrict__ xph, char* __restrict__ w1ph,
            char* __restrict__ w2ph, char* __restrict__ pAph) {
    const int blk = blockIdx.x, tid = threadIdx.x;

    if (blk < NB_SX + NB_SW1 + NB_SW2) {
        const float* src;
        char* dst;
        int K, R;
        long pb;
        int i;
        if (blk < NB_SX) {
            i = blk * 256 + tid;
            src = x; dst = xph; K = DIN; R = TT; pb = PB_X;
        } else if (blk < NB_SX + NB_SW1) {
            i = (blk - NB_SX) * 256 + tid;
            src = w1_w; dst = w1ph; K = DIN; R = CH; pb = 0;
        } else {
            i = (blk - NB_SX - NB_SW1) * 256 + tid;
            src = w2_w; dst = w2ph; K = OO; R = DIN; pb = 0;
        }
        long e = (long)i * 4;
        long perb = (long)R * K;
        int bb = (int)(e / perb);
        long rem = e - (long)bb * perb;
        int r = (int)(rem / K), k = (int)(rem % K);
        float4 v = ((const float4*)src)[i];
        __half2 hA, hB;
        hA.x = __float2half(v.x); hA.y = __float2half(v.y);
        hB.x = __float2half(v.z); hB.y = __float2half(v.w);
        size_t off = (size_t)bb * pb + pk_off(r, k, K >> 5);
        uint2 hw;
        hw.x = *(uint32_t*)&hA; hw.y = *(uint32_t*)&hB;
        *(uint2*)(dst + off) = hw;
        return;
    }
    if (blk < NB_SX + NB_SW1 + NB_SW2 + NB_PA) {
        // quantize p_w[b][c][o] * pwn[b][o]
        int i = (blk - NB_SX - NB_SW1 - NB_SW2) * 256 + tid;
        long e = (long)i * 4;
        long perb = (long)CH * OO;
        int bb = (int)(e / perb);
        long rem = e - (long)bb * perb;
        int c = (int)(rem / OO), o = (int)(rem % OO);
        float4 v = ((const float4*)p_w)[i];
        float4 s = *(const float4*)(g_pwn + (size_t)bb * OO + o);
        __half2 hA, hB;
        hA.x = __float2half(v.x * s.x); hA.y = __float2half(v.y * s.y);
        hB.x = __float2half(v.z * s.z); hB.y = __float2half(v.w * s.w);
        size_t off = (size_t)bb * PB_1K + pk_off(c, o, 32);
        uint2 hw;
        hw.x = *(uint32_t*)&hA; hw.y = *(uint32_t*)&hB;
        *(uint2*)(pAph + off) = hw;
        return;
    }
    {
        // bb2: block idx -> (b, i-group of 32)
        __shared__ float red[32][9];
        int idx = blk - (NB_SX + NB_SW1 + NB_SW2 + NB_PA);
        int b = idx >> 3, i0 = (idx & 7) * 32;
        int ii = tid >> 3, og = tid & 7;
        const float* pb = p_b + (size_t)b * OO;
        const float* w2r = w2_w + (size_t)(i0 + ii) * OO;
        float s = 0.f;
        for (int o = og; o < OO; o += 8) s += pb[o] * w2r[o];
        red[ii][og] = s;
        __syncthreads();
        if (og == 0) {
            float t = 0.f;
            #pragma unroll
            for (int j = 0; j < 8; j++) t += red[ii][j];
            g_bb2[b * DIN + i0 + ii] = w2_b[i0 + ii] + t;
        }
    }
}

// ---------------------------------------------------------------------------
// Fused: depthwise conv (fp16 input) + transpose + fp16 quantize, packed out
// (p_g IS folded in here — the W-GEMM epilogue must NOT apply it again.)
// ---------------------------------------------------------------------------
__global__ void __launch_bounds__(256)
convT_kernel(const float* __restrict__ d_w, const float* __restrict__ d_g,
             const float* __restrict__ d_b, const float* __restrict__ p_g,
             char* __restrict__ hi) {
    __shared__ float tile[32][41];
    int b = blockIdx.z, c0 = blockIdx.y * 32, t0 = blockIdx.x * 32;
    int tid = threadIdx.x;

    const __half* hbase = g_h + ((size_t)b * CH + c0) * TT;
    #pragma unroll
    for (int i = tid; i < 320; i += 256) {
        int c = i / 10, q = i - c * 10;
        int t = t0 - 4 + q * 4;
        if (t >= 0 && t + 3 < TT) {
            uint2 u = *(const uint2*)(hbase + (size_t)c * TT + t);
            __half2 p0 = *(__half2*)&u.x, p1 = *(__half2*)&u.y;
            tile[c][q * 4 + 0] = __half2float(p0.x);
            tile[c][q * 4 + 1] = __half2float(p0.y);
            tile[c][q * 4 + 2] = __half2float(p1.x);
            tile[c][q * 4 + 3] = __half2float(p1.y);
        } else {
            #pragma unroll
            for (int e = 0; e < 4; e++) {
                int tt = t + e;
                tile[c][q * 4 + e] = (tt >= 0 && tt < TT)
                    ? __half2float(hbase[(size_t)c * TT + tt]) : 0.f;
            }
        }
    }
    __syncthreads();

    int kp = tid & 15, tr = tid >> 4;
    int ca = c0 + 2 * kp;
    float ga = d_g[b * CH + ca],     gb = d_g[b * CH + ca + 1];
    float pa = p_g[b * CH + ca],     pb = p_g[b * CH + ca + 1];
    float b0 = d_b[b * CH + ca],     b1 = d_b[b * CH + ca + 1];
    float wa[KW], wb[KW];
    #pragma unroll
    for (int k = 0; k < KW; k++) {
        float dn = g_dwn[b * KW + k];
        wa[k] = d_w[((size_t)b * CH + ca) * KW + k]     * dn * ga;
        wb[k] = d_w[((size_t)b * CH + ca + 1) * KW + k] * dn * gb;
    }

    #pragma unroll
    for (int it = 0; it < 2; it++) {
        int tl = tr + it * 16;
        float a0 = b0, a1 = b1;
        #pragma unroll
        for (int k = 0; k < KW; k++) {
            a0 = fmaf(tile[2 * kp][tl + k],     wa[k], a0);
            a1 = fmaf(tile[2 * kp + 1][tl + k], wb[k], a1);
        }
        __half2 hv;
        hv.x = __float2half(a0 * pa);
        hv.y = __float2half(a1 * pb);
        size_t off = (size_t)b * PB_1K + pk_off(t0 + tl, ca, 32);
        *(__half2*)(hi + off) = hv;
    }
}

// ---------------------------------------------------------------------------
// PTX helpers
// ---------------------------------------------------------------------------
__device__ __forceinline__ uint32_t smem_u32(const void* p) {
    uint32_t a;
    asm("{ .reg .u64 t; cvta.to.shared.u64 t, %1; cvt.u32.u64 %0, t; }"
        : "=r"(a) : "l"(p));
    return a;
}

__device__ __forceinline__ void mbar_init(uint32_t m, uint32_t cnt) {
    asm volatile("mbarrier.init.shared.b64 [%0], %1;" :: "r"(m), "r"(cnt)
                 : "memory");
}

__device__ __forceinline__ void mbar_expect(uint32_t m, uint32_t tx) {
    asm volatile("mbarrier.arrive.expect_tx.shared.b64 _, [%0], %1;"
                 :: "r"(m), "r"(tx) : "memory");
}

__device__ __forceinline__ void mbar_arrive(uint32_t m) {
    asm volatile("mbarrier.arrive.shared.b64 _, [%0];" :: "r"(m) : "memory");
}

__device__ __forceinline__ void bulk_g2s(uint32_t dst, const void* src,
                                         uint32_t bytes, uint32_t mbar) {
    asm volatile(
        "cp.async.bulk.shared::cluster.global.mbarrier::complete_tx::bytes "
        "[%0], [%1], %2, [%3];"
        :: "r"(dst), "l"(src), "r"(bytes), "r"(mbar) : "memory");
}

__device__ __forceinline__ void mbar_wait(uint32_t m, uint32_t parity) {
    uint32_t done = 0;
    while (!done)
        asm volatile(
            "{ .reg .pred P; mbarrier.try_wait.parity.shared.b64 P, [%1], %2; "
            "selp.b32 %0,1,0,P; }"
            : "=r"(done) : "r"(m), "r"(parity) : "memory");
}

__device__ __forceinline__ void ldsm4(uint32_t* r, uint32_t a) {
    asm volatile("ldmatrix.sync.aligned.m8n8.x4.shared.b16 {%0,%1,%2,%3}, [%4];"
                 : "=r"(r[0]), "=r"(r[1]), "=r"(r[2]), "=r"(r[3]) : "r"(a));
}

__device__ __forceinline__ void ldsm2(uint32_t* r, uint32_t a) {
    asm volatile("ldmatrix.sync.aligned.m8n8.x2.shared.b16 {%0,%1}, [%2];"
                 : "=r"(r[0]), "=r"(r[1]) : "r"(a));
}

__device__ __forceinline__ void mma16816(float* d, const uint32_t* a,
                                         const uint32_t* b) {
    asm volatile(
        "mma.sync.aligned.m16n8k16.row.col.f32.f16.f16.f32 "
        "{%0,%1,%2,%3}, {%4,%5,%6,%7}, {%8,%9}, {%0,%1,%2,%3};"
        : "+f"(d[0]), "+f"(d[1]), "+f"(d[2]), "+f"(d[3])
        : "r"(a[0]), "r"(a[1]), "r"(a[2]), "r"(a[3]), "r"(b[0]), "r"(b[1]));
}

// ---------------------------------------------------------------------------
// Single-pass fp16 GEMM, producer-consumer pipeline.
// EPI 1: fp16 C = mish(v + e1[m])                     (GEMM1)
// EPI 3: fp32 C = v + e1[b*N+n] + e2[b][m][n]         (final; e1 = bb2)
// EPI 4: packed fp16 C = v                            (W-GEMM; NO extra scale
//        — p_g is already folded into y by convT_kernel)
// ---------------------------------------------------------------------------
#define ASEG  SEGB                       // A: 128 rows

template<int EPI, int NJ, int NS>
__global__ void __launch_bounds__(256, 2)
mma_gemm(const char* __restrict__ Ah, long sA,
         const char* __restrict__ Bh, long sB,
         void* __restrict__ C0, long sC,
         int M, int N, int K,
         const float* __restrict__ e1, const float* __restrict__ e2)
{
    constexpr int BN   = 32 * NJ;
    constexpr int BSEG = BN * PROWB;
    constexpr int STG  = ASEG + BSEG;

    extern __shared__ __align__(128) char sm[];
    const uint32_t smb = smem_u32(sm);
    const uint32_t mbF = smb + NS * STG;
    const uint32_t mbE = mbF + NS * 8;
    const int tid = threadIdx.x, lane = tid & 31, wid = tid >> 5;
    const int b = blockIdx.z;
    const int m0 = blockIdx.y * 128, n0 = blockIdx.x * BN;
    const int wm = wid >> 2, wn = wid & 3;
    const int nk = K >> 5;

    const char* pAh = Ah + (size_t)b * sA + (size_t)(m0 >> 7) * nk * SEGB;
    const char* pBh = Bh + (size_t)b * sB + (size_t)(n0 >> 7) * nk * SEGB
                         + (size_t)(n0 & 127) * PROWB;

    if (tid < NS) {
        mbar_init(mbF + tid * 8, 1);
        mbar_init(mbE + tid * 8, 8);
    }
    __syncthreads();

    float acc[4][NJ][4];
    #pragma unroll
    for (int i = 0; i < 4; i++)
        #pragma unroll
        for (int j = 0; j < NJ; j++)
            #pragma unroll
            for (int r = 0; r < 4; r++) acc[i][j][r] = 0.f;

    auto issue = [&](int kc) {
        int s = kc % NS;
        uint32_t mb = mbF + s * 8;
        uint32_t sb = smb + s * STG;
        size_t go = (size_t)kc * SEGB;
        mbar_expect(mb, STG);
        bulk_g2s(sb,        pAh + go, ASEG, mb);
        bulk_g2s(sb + ASEG, pBh + go, BSEG, mb);
    };

    auto compute = [&](int s) {
        const uint32_t sb = smb + s * STG;
        #pragma unroll
        for (int ks = 0; ks < 2; ks++) {
            uint32_t ah[4][4], bh[NJ][2];
            #pragma unroll
            for (int i = 0; i < 4; i++) {
                uint32_t ad = sb +
                    (uint32_t)((wm * 64 + i * 16 + (lane & 15)) * PROWB) +
                    ks * 32 + (lane >> 4) * 16;
                ldsm4(ah[i], ad);
            }
            #pragma unroll
            for (int j = 0; j < NJ; j++) {
                uint32_t bd = sb + ASEG +
                    (uint32_t)((wn * (BN / 4) + j * 8 + (lane & 7)) * PROWB) +
                    ks * 32 + ((lane >> 3) & 1) * 16;
                ldsm2(bh[j], bd);
            }
            #pragma unroll
            for (int i = 0; i < 4; i++)
                #pragma unroll
                for (int j = 0; j < NJ; j++)
                    mma16816(acc[i][j], ah[i], bh[j]);
        }
    };

    if (tid == 0) {
        #pragma unroll
        for (int p = 0; p < NS - 1; p++)
            if (p < nk) issue(p);
    }
    for (int kc = 0; kc < nk; kc++) {
        int s = kc % NS;
        mbar_wait(mbF + s * 8, (kc / NS) & 1);
        compute(s);
        if (lane == 0) mbar_arrive(mbE + s * 8);
        int kn = kc + NS - 1;
        if (kn < nk && tid == 0) {
            int sn = kn % NS;
            if (kn >= NS)
                mbar_wait(mbE + sn * 8, (kn / NS - 1) & 1);
            issue(kn);
        }
    }

    // --- epilogue ---
    const float* E1 = e1;
    const float* E2 = e2;
    if (EPI == 3) { E1 = e1 + b * N; E2 = e2 + (size_t)b * M * N; }

    char* C0b = (char*)C0 + (size_t)b * sC;

    const int mrow0 = m0 + wm * 64;
    const int ncol0 = n0 + wn * (BN / 4);
    #pragma unroll
    for (int i = 0; i < 4; i++) {
        #pragma unroll
        for (int r = 0; r < 2; r++) {
            int m = mrow0 + i * 16 + (lane >> 2) + r * 8;
            #pragma unroll
            for (int j = 0; j < NJ; j++) {
                int n = ncol0 + j * 8 + (lane & 3) * 2;
                float v0 = acc[i][j][r * 2 + 0];
                float v1 = acc[i][j][r * 2 + 1];
                size_t off = (size_t)m * N + n;
                if (EPI == 1) {
                    float bb = E1[m];
                    __half2 hv;
                    hv.x = __float2half(mishf(v0 + bb));
                    hv.y = __float2half(mishf(v1 + bb));
                    *(__half2*)((__half*)C0b + off) = hv;
                } else if (EPI == 3) {
                    float2 o;
                    o.x = v0 + E1[n]     + E2[off];
                    o.y = v1 + E1[n + 1] + E2[off + 1];
                    *(float2*)((float*)C0b + off) = o;
                } else if (EPI == 4) {
                    __half2 hv;
                    hv.x = __float2half(v0);
                    hv.y = __float2half(v1);
                    size_t po = pk_off(m, n, N >> 5);
                    *(uint32_t*)(C0b + po) = *(uint32_t*)&hv;
                }
            }
        }
    }
}

#define SMEM_OF(NJ_, NS_) ((NS_) * (ASEG + 32 * (NJ_) * PROWB) + 2 * (NS_) * 8)

// ---------------------------------------------------------------------------
extern "C" void kernel_launch(void* const* d_in, const int* in_sizes, int n_in,
                              void* d_out, int out_size) {
    const float* x    = (const float*)d_in[0];
    const float* d_w  = (const float*)d_in[1];
    const float* d_g  = (const float*)d_in[2];
    const float* d_b  = (const float*)d_in[3];
    const float* p_w  = (const float*)d_in[4];
    const float* p_g  = (const float*)d_in[5];
    const float* p_b  = (const float*)d_in[6];
    const float* w1_w = (const float*)d_in[7];
    const float* w1_b = (const float*)d_in[8];
    const float* w2_w = (const float*)d_in[9];
    const float* w2_b = (const float*)d_in[10];
    float* out = (float*)d_out;

    void *p_gh, *p_bb2;
    void *p_xh, *p_w1h, *p_w2h, *p_pa, *p_yth, *p_wt;
    cudaGetSymbolAddress(&p_gh,  g_h);
    cudaGetSymbolAddress(&p_bb2, g_bb2);
    cudaGetSymbolAddress(&p_xh,  g_xph);
    cudaGetSymbolAddress(&p_w1h, g_w1ph);
    cudaGetSymbolAddress(&p_w2h, g_w2ph);
    cudaGetSymbolAddress(&p_pa,  g_pAph);
    cudaGetSymbolAddress(&p_yth, g_yTph);
    cudaGetSymbolAddress(&p_wt,  g_Wtph);

    cudaFuncSetAttribute((const void*)mma_gemm<1, 4, 4>,
                         cudaFuncAttributeMaxDynamicSharedMemorySize,
                         SMEM_OF(4, 4));
    cudaFuncSetAttribute((const void*)mma_gemm<4, 2, 4>,
                         cudaFuncAttributeMaxDynamicSharedMemorySize,
                         SMEM_OF(2, 4));
    cudaFuncSetAttribute((const void*)mma_gemm<3, 2, 6>,
                         cudaFuncAttributeMaxDynamicSharedMemorySize,
                         SMEM_OF(2, 6));

    // 1) norms (pwn needed by prep)
    norm_kernel<<<328, 256>>>(d_w, p_w);

    // 2) fused preprocessing
    prep_kernel<<<NB_TOT, 256>>>(x, p_w, w1_w, w2_w, p_b, w2_b,
                                 (char*)p_xh, (char*)p_w1h,
                                 (char*)p_w2h, (char*)p_pa);

    // 3) GEMM1: h = mish(w1 . x + w1_b)   M=CH, N=TT, K=DIN  (fp16 out)
    {
        dim3 grid(TT / 128, CH / 128, BB);
        mma_gemm<1, 4, 4><<<grid, 256, SMEM_OF(4, 4)>>>(
            (char*)p_w1h, 0L,
            (char*)p_xh, (long)PB_X,
            p_gh, (long)CH * TT * 2,
            CH, TT, DIN, w1_b, nullptr);
    }

    // 4) fused conv + transpose + fp16 quantize (p_g folded) -> yT packed
    {
        dim3 grid(TT / 32, CH / 32, BB);
        convT_kernel<<<grid, 256>>>(d_w, d_g, d_b, p_g, (char*)p_yth);
    }

    // 5) W-GEMM: Wt[i][c] = sum_o w2[i][o] * pA[c][o]
    //    M=DIN(i), N=CH(c), K=OO(o); packed fp16 out [i][c] (no scale)
    {
        dim3 grid(CH / 64, DIN / 128, BB);
        mma_gemm<4, 2, 4><<<grid, 256, SMEM_OF(2, 4)>>>(
            (char*)p_w2h, 0L,
            (char*)p_pa, (long)PB_1K,
            p_wt, (long)PB_W2,
            DIN, CH, OO, nullptr, nullptr);
    }

    // 6) final: out[t][i] = yT . Wt + bb2[b][i] + x   M=TT, N=DIN, K=CH
    {
        dim3 grid(DIN / 64, TT / 128, BB);
        mma_gemm<3, 2, 6><<<grid, 256, SMEM_OF(2, 6)>>>(
            (char*)p_yth, (long)PB_1K,
            (char*)p_wt, (long)PB_W2,
            out, (long)TT * DIN * 4,
            TT, DIN, CH, (const float*)p_bb2, x);
    }
}

// round 17
// speedup vs baseline: 1.3609x; 1.0820x over previous
#include <cuda_runtime.h>
#include <cuda_fp16.h>
#include <math.h>
#include <stdint.h>

// Problem constants
#define BB   8
#define TT   1024
#define DIN  256
#define CH   1024   // D_H1
#define OO   1024   // D_H2
#define KW   9

// Packed-panel format for GEMM operands (fp16, 2 bytes):
//   operand [R][K] (K-major) -> tiles of 128 rows x 32 k,
//   byte offset = ((r>>7)*nks + (k>>5))*SEGB + (r&127)*PROWB + (k&31)*2
#define PROWB 80
#define SEGB  10240                     // 128 * 80
#define PB_X   (8 * 8 * SEGB)           // per-batch packed x   [1024][256]
#define PB_1K  (8 * 32 * SEGB)          // per-batch packed [1024][1024]
#define PB_W2  (2 * 32 * SEGB)          // packed [256][1024]

__device__ __forceinline__ size_t pk_off(int r, int k, int nks) {
    return (size_t)((r >> 7) * nks + (k >> 5)) * SEGB +
           (size_t)(r & 127) * PROWB + (size_t)(k & 31) * 2;
}

// Scratch (device globals — no allocation allowed)
__device__ __half g_h [BB * CH * TT];    // mish(w1(x)), [b][c][t], fp16
__device__ float g_pwn[BB * OO];         // 1/||p_w[b,:,o]||
__device__ float g_dwn[BB * KW];
__device__ float g_bb2[BB * DIN];        // w2_b[i] + sum_o p_b[o] w2[i][o]
__device__ __align__(128) char g_xph [BB * PB_X];    // B of GEMM1
__device__ __align__(128) char g_w1ph[8 * 8 * SEGB]; // A of GEMM1
__device__ __align__(128) char g_w2ph[PB_W2];        // A of W-GEMM [i][o]
__device__ __align__(128) char g_pAph[BB * PB_1K];   // B of W-GEMM: p_w*pwn [c][o]
__device__ __align__(128) char g_yTph[BB * PB_1K];   // A of final GEMM [t][c]
__device__ __align__(128) char g_Wtph[BB * PB_W2];   // B of final GEMM [i][c]

// Fast mish
__device__ __forceinline__ float mishf(float v) {
    if (v > 20.f) return v;
    float u = __expf(v);
    float w = u * (u + 2.f);
    return v * w * __frcp_rn(w + 2.f);
}

// ---------------------------------------------------------------------------
// Norm kernel (must precede prep: prep consumes g_pwn)
// ---------------------------------------------------------------------------
__global__ void __launch_bounds__(256)
norm_kernel(const float* __restrict__ d_w, const float* __restrict__ p_w) {
    __shared__ float red2[8][33];
    const int blk = blockIdx.x, tid = threadIdx.x;
    if (blk < 72) {
        __shared__ float red[256];
        int b = blk / KW, k = blk % KW;
        float s = 0.f;
        for (int c = tid; c < CH; c += 256) {
            float v = d_w[((long)b * CH + c) * KW + k];
            s += v * v;
        }
        red[tid] = s;
        __syncthreads();
        for (int off = 128; off > 0; off >>= 1) {
            if (tid < off) red[tid] += red[tid + off];
            __syncthreads();
        }
        if (tid == 0)
            g_dwn[b * KW + k] = 1.f / fmaxf(sqrtf(red[0]), 1e-12f);
        return;
    }
    int idx = blk - 72;
    int b  = idx / (OO / 32);
    int o0 = (idx % (OO / 32)) * 32;
    int oi = tid & 31, cg = tid >> 5;
    int o = o0 + oi;
    float s = 0.f;
    for (int c = cg; c < CH; c += 8) {
        float v = p_w[((long)b * CH + c) * OO + o];
        s += v * v;
    }
    red2[cg][oi] = s;
    __syncthreads();
    if (cg == 0) {
        float t = 0.f;
        #pragma unroll
        for (int j = 0; j < 8; j++) t += red2[j][oi];
        g_pwn[b * OO + o] = 1.f / fmaxf(sqrtf(t), 1e-12f);
    }
}

// ---------------------------------------------------------------------------
// Fused preprocessing (after norm_kernel)
// ---------------------------------------------------------------------------
#define NB_SX   2048
#define NB_SW1  256
#define NB_SW2  256
#define NB_PA   8192
#define NB_BB2  64
#define NB_TOT  (NB_SX + NB_SW1 + NB_SW2 + NB_PA + NB_BB2)

__global__ void __launch_bounds__(256)
prep_kernel(const float* __restrict__ x,
            const float* __restrict__ p_w,
            const float* __restrict__ w1_w,
            const float* __restrict__ w2_w,
            const float* __restrict__ p_b,
            const float* __restrict__ w2_b,
            char* __restrict__ xph, char* __restrict__ w1ph,
            char* __restrict__ w2ph, char* __restrict__ pAph) {
    const int blk = blockIdx.x, tid = threadIdx.x;

    if (blk < NB_SX + NB_SW1 + NB_SW2) {
        const float* src;
        char* dst;
        int K, R;
        long pb;
        int i;
        if (blk < NB_SX) {
            i = blk * 256 + tid;
            src = x; dst = xph; K = DIN; R = TT; pb = PB_X;
        } else if (blk < NB_SX + NB_SW1) {
            i = (blk - NB_SX) * 256 + tid;
            src = w1_w; dst = w1ph; K = DIN; R = CH; pb = 0;
        } else {
            i = (blk - NB_SX - NB_SW1) * 256 + tid;
            src = w2_w; dst = w2ph; K = OO; R = DIN; pb = 0;
        }
        long e = (long)i * 4;
        long perb = (long)R * K;
        int bb = (int)(e / perb);
        long rem = e - (long)bb * perb;
        int r = (int)(rem / K), k = (int)(rem % K);
        float4 v = ((const float4*)src)[i];
        __half2 hA, hB;
        hA.x = __float2half(v.x); hA.y = __float2half(v.y);
        hB.x = __float2half(v.z); hB.y = __float2half(v.w);
        size_t off = (size_t)bb * pb + pk_off(r, k, K >> 5);
        uint2 hw;
        hw.x = *(uint32_t*)&hA; hw.y = *(uint32_t*)&hB;
        *(uint2*)(dst + off) = hw;
        return;
    }
    if (blk < NB_SX + NB_SW1 + NB_SW2 + NB_PA) {
        int i = (blk - NB_SX - NB_SW1 - NB_SW2) * 256 + tid;
        long e = (long)i * 4;
        long perb = (long)CH * OO;
        int bb = (int)(e / perb);
        long rem = e - (long)bb * perb;
        int c = (int)(rem / OO), o = (int)(rem % OO);
        float4 v = ((const float4*)p_w)[i];
        float4 s = *(const float4*)(g_pwn + (size_t)bb * OO + o);
        __half2 hA, hB;
        hA.x = __float2half(v.x * s.x); hA.y = __float2half(v.y * s.y);
        hB.x = __float2half(v.z * s.z); hB.y = __float2half(v.w * s.w);
        size_t off = (size_t)bb * PB_1K + pk_off(c, o, 32);
        uint2 hw;
        hw.x = *(uint32_t*)&hA; hw.y = *(uint32_t*)&hB;
        *(uint2*)(pAph + off) = hw;
        return;
    }
    {
        __shared__ float red[32][9];
        int idx = blk - (NB_SX + NB_SW1 + NB_SW2 + NB_PA);
        int b = idx >> 3, i0 = (idx & 7) * 32;
        int ii = tid >> 3, og = tid & 7;
        const float* pb = p_b + (size_t)b * OO;
        const float* w2r = w2_w + (size_t)(i0 + ii) * OO;
        float s = 0.f;
        for (int o = og; o < OO; o += 8) s += pb[o] * w2r[o];
        red[ii][og] = s;
        __syncthreads();
        if (og == 0) {
            float t = 0.f;
            #pragma unroll
            for (int j = 0; j < 8; j++) t += red[ii][j];
            g_bb2[b * DIN + i0 + ii] = w2_b[i0 + ii] + t;
        }
    }
}

// ---------------------------------------------------------------------------
// Fused: depthwise conv + transpose + fp16 quantize, packed out.
// Register-sliding-window version: block = 32c x 64t, thread = (c-pair, t-quad)
// computing 4 consecutive t per channel from a 12-float window (3x LDS.128).
// p_g IS folded here.
// ---------------------------------------------------------------------------
#define CT_S 76      // padded row stride (floats), 304B, 16B-aligned

__global__ void __launch_bounds__(256)
convT_kernel(const float* __restrict__ d_w, const float* __restrict__ d_g,
             const float* __restrict__ d_b, const float* __restrict__ p_g,
             char* __restrict__ hi) {
    __shared__ __align__(16) float tile[32][CT_S];   // j: t0-4 .. t0+67
    int b = blockIdx.z, c0 = blockIdx.y * 32, t0 = blockIdx.x * 64;
    int tid = threadIdx.x;

    const __half* hbase = g_h + ((size_t)b * CH + c0) * TT;
    // stage 32 rows x 72 t (as 18 quads of 4 fp16)
    #pragma unroll
    for (int i = tid; i < 32 * 18; i += 256) {
        int c = i / 18, q = i - c * 18;
        int t = t0 - 4 + q * 4;
        if (t >= 0 && t + 3 < TT) {
            uint2 u = *(const uint2*)(hbase + (size_t)c * TT + t);
            __half2 p0 = *(__half2*)&u.x, p1 = *(__half2*)&u.y;
            tile[c][q * 4 + 0] = __half2float(p0.x);
            tile[c][q * 4 + 1] = __half2float(p0.y);
            tile[c][q * 4 + 2] = __half2float(p1.x);
            tile[c][q * 4 + 3] = __half2float(p1.y);
        } else {
            #pragma unroll
            for (int e = 0; e < 4; e++) {
                int tt = t + e;
                tile[c][q * 4 + e] = (tt >= 0 && tt < TT)
                    ? __half2float(hbase[(size_t)c * TT + tt]) : 0.f;
            }
        }
    }
    __syncthreads();

    int kp = tid & 15, tq = tid >> 4;    // c-pair, t-quad (4 consecutive t)
    int ca = c0 + 2 * kp;
    float ga = d_g[b * CH + ca],     gb = d_g[b * CH + ca + 1];
    float pa = p_g[b * CH + ca],     pb = p_g[b * CH + ca + 1];
    float b0 = d_b[b * CH + ca],     b1 = d_b[b * CH + ca + 1];
    float wa[KW], wb[KW];
    #pragma unroll
    for (int k = 0; k < KW; k++) {
        float dn = g_dwn[b * KW + k];
        wa[k] = d_w[((size_t)b * CH + ca) * KW + k]     * dn * ga;
        wb[k] = d_w[((size_t)b * CH + ca + 1) * KW + k] * dn * gb;
    }

    // 12-float windows, 3x float4 each channel
    float wA[12], wB[12];
    {
        const float* rA = &tile[2 * kp][4 * tq];
        const float* rB = &tile[2 * kp + 1][4 * tq];
        *(float4*)&wA[0] = *(const float4*)&rA[0];
        *(float4*)&wA[4] = *(const float4*)&rA[4];
        *(float4*)&wA[8] = *(const float4*)&rA[8];
        *(float4*)&wB[0] = *(const float4*)&rB[0];
        *(float4*)&wB[4] = *(const float4*)&rB[4];
        *(float4*)&wB[8] = *(const float4*)&rB[8];
    }

    #pragma unroll
    for (int i = 0; i < 4; i++) {
        float a0 = b0, a1 = b1;
        #pragma unroll
        for (int k = 0; k < KW; k++) {
            a0 = fmaf(wA[i + k], wa[k], a0);
            a1 = fmaf(wB[i + k], wb[k], a1);
        }
        __half2 hv;
        hv.x = __float2half(a0 * pa);
        hv.y = __float2half(a1 * pb);
        size_t off = (size_t)b * PB_1K + pk_off(t0 + 4 * tq + i, ca, 32);
        *(__half2*)(hi + off) = hv;
    }
}

// ---------------------------------------------------------------------------
// PTX helpers
// ---------------------------------------------------------------------------
__device__ __forceinline__ uint32_t smem_u32(const void* p) {
    uint32_t a;
    asm("{ .reg .u64 t; cvta.to.shared.u64 t, %1; cvt.u32.u64 %0, t; }"
        : "=r"(a) : "l"(p));
    return a;
}

__device__ __forceinline__ void mbar_init(uint32_t m, uint32_t cnt) {
    asm volatile("mbarrier.init.shared.b64 [%0], %1;" :: "r"(m), "r"(cnt)
                 : "memory");
}

__device__ __forceinline__ void mbar_expect(uint32_t m, uint32_t tx) {
    asm volatile("mbarrier.arrive.expect_tx.shared.b64 _, [%0], %1;"
                 :: "r"(m), "r"(tx) : "memory");
}

__device__ __forceinline__ void mbar_arrive(uint32_t m) {
    asm volatile("mbarrier.arrive.shared.b64 _, [%0];" :: "r"(m) : "memory");
}

__device__ __forceinline__ void bulk_g2s(uint32_t dst, const void* src,
                                         uint32_t bytes, uint32_t mbar) {
    asm volatile(
        "cp.async.bulk.shared::cluster.global.mbarrier::complete_tx::bytes "
        "[%0], [%1], %2, [%3];"
        :: "r"(dst), "l"(src), "r"(bytes), "r"(mbar) : "memory");
}

__device__ __forceinline__ void mbar_wait(uint32_t m, uint32_t parity) {
    uint32_t done = 0;
    while (!done)
        asm volatile(
            "{ .reg .pred P; mbarrier.try_wait.parity.shared.b64 P, [%1], %2; "
            "selp.b32 %0,1,0,P; }"
            : "=r"(done) : "r"(m), "r"(parity) : "memory");
}

__device__ __forceinline__ void ldsm4(uint32_t* r, uint32_t a) {
    asm volatile("ldmatrix.sync.aligned.m8n8.x4.shared.b16 {%0,%1,%2,%3}, [%4];"
                 : "=r"(r[0]), "=r"(r[1]), "=r"(r[2]), "=r"(r[3]) : "r"(a));
}

__device__ __forceinline__ void ldsm2(uint32_t* r, uint32_t a) {
    asm volatile("ldmatrix.sync.aligned.m8n8.x2.shared.b16 {%0,%1}, [%2];"
                 : "=r"(r[0]), "=r"(r[1]) : "r"(a));
}

__device__ __forceinline__ void mma16816(float* d, const uint32_t* a,
                                         const uint32_t* b) {
    asm volatile(
        "mma.sync.aligned.m16n8k16.row.col.f32.f16.f16.f32 "
        "{%0,%1,%2,%3}, {%4,%5,%6,%7}, {%8,%9}, {%0,%1,%2,%3};"
        : "+f"(d[0]), "+f"(d[1]), "+f"(d[2]), "+f"(d[3])
        : "r"(a[0]), "r"(a[1]), "r"(a[2]), "r"(a[3]), "r"(b[0]), "r"(b[1]));
}

// ---------------------------------------------------------------------------
// Single-pass fp16 GEMM, producer-consumer pipeline.
// EPI 1: fp16 C = mish(v + e1[m])                     (GEMM1)
// EPI 3: fp32 C = v + e1[b*N+n] + e2[b][m][n]         (final; e1 = bb2)
// EPI 4: packed fp16 C = v                            (W-GEMM)
// ---------------------------------------------------------------------------
#define ASEG  SEGB                       // A: 128 rows

template<int EPI, int NJ, int NS>
__global__ void __launch_bounds__(256, 2)
mma_gemm(const char* __restrict__ Ah, long sA,
         const char* __restrict__ Bh, long sB,
         void* __restrict__ C0, long sC,
         int M, int N, int K,
         const float* __restrict__ e1, const float* __restrict__ e2)
{
    constexpr int BN   = 32 * NJ;
    constexpr int BSEG = BN * PROWB;
    constexpr int STG  = ASEG + BSEG;

    extern __shared__ __align__(128) char sm[];
    const uint32_t smb = smem_u32(sm);
    const uint32_t mbF = smb + NS * STG;
    const uint32_t mbE = mbF + NS * 8;
    const int tid = threadIdx.x, lane = tid & 31, wid = tid >> 5;
    const int b = blockIdx.z;
    const int m0 = blockIdx.y * 128, n0 = blockIdx.x * BN;
    const int wm = wid >> 2, wn = wid & 3;
    const int nk = K >> 5;

    const char* pAh = Ah + (size_t)b * sA + (size_t)(m0 >> 7) * nk * SEGB;
    const char* pBh = Bh + (size_t)b * sB + (size_t)(n0 >> 7) * nk * SEGB
                         + (size_t)(n0 & 127) * PROWB;

    if (tid < NS) {
        mbar_init(mbF + tid * 8, 1);
        mbar_init(mbE + tid * 8, 8);
    }
    __syncthreads();

    float acc[4][NJ][4];
    #pragma unroll
    for (int i = 0; i < 4; i++)
        #pragma unroll
        for (int j = 0; j < NJ; j++)
            #pragma unroll
            for (int r = 0; r < 4; r++) acc[i][j][r] = 0.f;

    auto issue = [&](int kc) {
        int s = kc % NS;
        uint32_t mb = mbF + s * 8;
        uint32_t sb = smb + s * STG;
        size_t go = (size_t)kc * SEGB;
        mbar_expect(mb, STG);
        bulk_g2s(sb,        pAh + go, ASEG, mb);
        bulk_g2s(sb + ASEG, pBh + go, BSEG, mb);
    };

    auto compute = [&](int s) {
        const uint32_t sb = smb + s * STG;
        #pragma unroll
        for (int ks = 0; ks < 2; ks++) {
            uint32_t ah[4][4], bh[NJ][2];
            #pragma unroll
            for (int i = 0; i < 4; i++) {
                uint32_t ad = sb +
                    (uint32_t)((wm * 64 + i * 16 + (lane & 15)) * PROWB) +
                    ks * 32 + (lane >> 4) * 16;
                ldsm4(ah[i], ad);
            }
            #pragma unroll
            for (int j = 0; j < NJ; j++) {
                uint32_t bd = sb + ASEG +
                    (uint32_t)((wn * (BN / 4) + j * 8 + (lane & 7)) * PROWB) +
                    ks * 32 + ((lane >> 3) & 1) * 16;
                ldsm2(bh[j], bd);
            }
            #pragma unroll
            for (int i = 0; i < 4; i++)
                #pragma unroll
                for (int j = 0; j < NJ; j++)
                    mma16816(acc[i][j], ah[i], bh[j]);
        }
    };

    if (tid == 0) {
        #pragma unroll
        for (int p = 0; p < NS - 1; p++)
            if (p < nk) issue(p);
    }
    for (int kc = 0; kc < nk; kc++) {
        int s = kc % NS;
        mbar_wait(mbF + s * 8, (kc / NS) & 1);
        compute(s);
        if (lane == 0) mbar_arrive(mbE + s * 8);
        int kn = kc + NS - 1;
        if (kn < nk && tid == 0) {
            int sn = kn % NS;
            if (kn >= NS)
                mbar_wait(mbE + sn * 8, (kn / NS - 1) & 1);
            issue(kn);
        }
    }

    // --- epilogue ---
    const float* E1 = e1;
    const float* E2 = e2;
    if (EPI == 3) { E1 = e1 + b * N; E2 = e2 + (size_t)b * M * N; }

    char* C0b = (char*)C0 + (size_t)b * sC;

    const int mrow0 = m0 + wm * 64;
    const int ncol0 = n0 + wn * (BN / 4);
    #pragma unroll
    for (int i = 0; i < 4; i++) {
        #pragma unroll
        for (int r = 0; r < 2; r++) {
            int m = mrow0 + i * 16 + (lane >> 2) + r * 8;
            #pragma unroll
            for (int j = 0; j < NJ; j++) {
                int n = ncol0 + j * 8 + (lane & 3) * 2;
                float v0 = acc[i][j][r * 2 + 0];
                float v1 = acc[i][j][r * 2 + 1];
                size_t off = (size_t)m * N + n;
                if (EPI == 1) {
                    float bb = E1[m];
                    __half2 hv;
                    hv.x = __float2half(mishf(v0 + bb));
                    hv.y = __float2half(mishf(v1 + bb));
                    *(__half2*)((__half*)C0b + off) = hv;
                } else if (EPI == 3) {
                    float2 o;
                    o.x = v0 + E1[n]     + E2[off];
                    o.y = v1 + E1[n + 1] + E2[off + 1];
                    *(float2*)((float*)C0b + off) = o;
                } else if (EPI == 4) {
                    __half2 hv;
                    hv.x = __float2half(v0);
                    hv.y = __float2half(v1);
                    size_t po = pk_off(m, n, N >> 5);
                    *(uint32_t*)(C0b + po) = *(uint32_t*)&hv;
                }
            }
        }
    }
}

#define SMEM_OF(NJ_, NS_) ((NS_) * (ASEG + 32 * (NJ_) * PROWB) + 2 * (NS_) * 8)

// ---------------------------------------------------------------------------
extern "C" void kernel_launch(void* const* d_in, const int* in_sizes, int n_in,
                              void* d_out, int out_size) {
    const float* x    = (const float*)d_in[0];
    const float* d_w  = (const float*)d_in[1];
    const float* d_g  = (const float*)d_in[2];
    const float* d_b  = (const float*)d_in[3];
    const float* p_w  = (const float*)d_in[4];
    const float* p_g  = (const float*)d_in[5];
    const float* p_b  = (const float*)d_in[6];
    const float* w1_w = (const float*)d_in[7];
    const float* w1_b = (const float*)d_in[8];
    const float* w2_w = (const float*)d_in[9];
    const float* w2_b = (const float*)d_in[10];
    float* out = (float*)d_out;

    void *p_gh, *p_bb2;
    void *p_xh, *p_w1h, *p_w2h, *p_pa, *p_yth, *p_wt;
    cudaGetSymbolAddress(&p_gh,  g_h);
    cudaGetSymbolAddress(&p_bb2, g_bb2);
    cudaGetSymbolAddress(&p_xh,  g_xph);
    cudaGetSymbolAddress(&p_w1h, g_w1ph);
    cudaGetSymbolAddress(&p_w2h, g_w2ph);
    cudaGetSymbolAddress(&p_pa,  g_pAph);
    cudaGetSymbolAddress(&p_yth, g_yTph);
    cudaGetSymbolAddress(&p_wt,  g_Wtph);

    cudaFuncSetAttribute((const void*)mma_gemm<1, 4, 4>,
                         cudaFuncAttributeMaxDynamicSharedMemorySize,
                         SMEM_OF(4, 4));
    cudaFuncSetAttribute((const void*)mma_gemm<4, 2, 4>,
                         cudaFuncAttributeMaxDynamicSharedMemorySize,
                         SMEM_OF(2, 4));
    cudaFuncSetAttribute((const void*)mma_gemm<3, 2, 6>,
                         cudaFuncAttributeMaxDynamicSharedMemorySize,
                         SMEM_OF(2, 6));

    // 1) norms (pwn needed by prep)
    norm_kernel<<<328, 256>>>(d_w, p_w);

    // 2) fused preprocessing
    prep_kernel<<<NB_TOT, 256>>>(x, p_w, w1_w, w2_w, p_b, w2_b,
                                 (char*)p_xh, (char*)p_w1h,
                                 (char*)p_w2h, (char*)p_pa);

    // 3) GEMM1: h = mish(w1 . x + w1_b)   M=CH, N=TT, K=DIN  (fp16 out)
    {
        dim3 grid(TT / 128, CH / 128, BB);
        mma_gemm<1, 4, 4><<<grid, 256, SMEM_OF(4, 4)>>>(
            (char*)p_w1h, 0L,
            (char*)p_xh, (long)PB_X,
            p_gh, (long)CH * TT * 2,
            CH, TT, DIN, w1_b, nullptr);
    }

    // 4) fused conv + transpose + fp16 quantize (p_g folded) -> yT packed
    {
        dim3 grid(TT / 64, CH / 32, BB);
        convT_kernel<<<grid, 256>>>(d_w, d_g, d_b, p_g, (char*)p_yth);
    }

    // 5) W-GEMM: Wt[i][c] = sum_o w2[i][o] * pA[c][o]
    //    M=DIN(i), N=CH(c), K=OO(o); packed fp16 out [i][c]
    {
        dim3 grid(CH / 64, DIN / 128, BB);
        mma_gemm<4, 2, 4><<<grid, 256, SMEM_OF(2, 4)>>>(
            (char*)p_w2h, 0L,
            (char*)p_pa, (long)PB_1K,
            p_wt, (long)PB_W2,
            DIN, CH, OO, nullptr, nullptr);
    }

    // 6) final: out[t][i] = yT . Wt + bb2[b][i] + x   M=TT, N=DIN, K=CH
    {
        dim3 grid(DIN / 64, TT / 128, BB);
        mma_gemm<3, 2, 6><<<grid, 256, SMEM_OF(2, 6)>>>(
            (char*)p_yth, (long)PB_1K,
            (char*)p_wt, (long)PB_W2,
            out, (long)TT * DIN * 4,
            TT, DIN, CH, (const float*)p_bb2, x);
    }
}